// round 11
// baseline (speedup 1.0000x reference)
#include <cuda_runtime.h>
#include <cuda_bf16.h>
#include <cstdint>

// ---------------------------------------------------------------------------
// Problem constants
// ---------------------------------------------------------------------------
#define BSZ    4096
#define ITEMW  10242
#define KT2    10496      // padded K: 128 (genre) + 2304 (director) + 8064 (actor)
#define NST    82         // 128-k steps; genre {0}, director [1,19), actor [19,82)
#define NSLOT  8          // 0=genre, 1-2=director, 3-7=actor
#define PCX    64         // numerator columns per slot

// K1 smem geometry
#define AST    544            // raw A row stride bytes (128 ints + 8 pad ints)
#define ATILE  (64 * AST)     // 34816 B per raw-A stage
#define BSTR   272            // B row stride bytes (128 bf16 + 16 pad)
#define BTILE  (64 * BSTR)    // 17408 B per B stage
#define K1SMEM (4 * ATILE + 4 * BTILE)   // 208896 B

// ---------------------------------------------------------------------------
// Device scratch (static globals; no allocations anywhere)
// ---------------------------------------------------------------------------
__device__ __align__(16) __nv_bfloat16 g_WT[64 * KT2];      // fused weights [d][k]
__device__ float g_UF[3528 * 64];                            // user folds
__device__ float g_RF[6 * 64];                               // rate_tab @ item_W[0:64]
__device__ float g_part[(size_t)NSLOT * BSZ * PCX];          // GEMM partial numerators
__device__ float g_cnt[NSLOT * BSZ];                         // per-field bit counts
__device__ float g_X[BSZ * 64], g_Y[BSZ * 64];               // x, y vectors
__device__ float g_S[BSZ * 8];                               // per-row scalars (6 used)
__device__ float g_SP[4 * 1024 * 64];                        // per-CTA partials of s1..s4
__device__ float g_SP2[4 * 16 * 64];                         // stage-2 partials
__device__ float g_U[4 * 64];                                // u1..u4
__device__ float g_O3[64];                                   // edge-branch output row
__device__ int   g_dummy[1];

// ---------------------------------------------------------------------------
// Dummy kernel: keeps ncu's capture slot on k1_gemm.
// ---------------------------------------------------------------------------
__global__ void k_dummy() { g_dummy[0] = 1; }

// ---------------------------------------------------------------------------
// K0a: fold item-side weights into g_WT (bf16).
//   WT k-layout bakes the raw-load shifts in:
//     genre   region k [0,128):     bit kr = k - 1     (item col k)
//     director region k [128,2432): bit kr = k - 130   (item col k - 104)
//     actor   region k [2432,10496): bit kr = k - 2432 (item col k - 220)
//   Out-of-range kr -> weight 0 (absorbs garbage bits from shifted loads).
// ---------------------------------------------------------------------------
__global__ void __launch_bounds__(256) k0_wt(
    const float* __restrict__ genre_W, const float* __restrict__ director_W,
    const float* __restrict__ actor_W, const float* __restrict__ item_W)
{
    __shared__ float s_iw[64][65];
    __shared__ float s_w[64][65];
    int tid = threadIdx.x, d = tid & 63, q = tid >> 6;
    int blk = blockIdx.x;           // 0..163
    int kb = blk * 64;
    const float* W; int len, iwo, kr0;
    if (blk < 2)       { W = genre_W;    len = 25;   iwo = 64;  kr0 = 1;    }
    else if (blk < 38) { W = director_W; len = 2186; iwo = 128; kr0 = 130;  }
    else               { W = actor_W;    len = 8030; iwo = 192; kr0 = 2432; }

    #pragma unroll
    for (int j = q; j < 64; j += 4) s_iw[j][d] = item_W[(iwo + j) * 64 + d];
    #pragma unroll
    for (int kk = q; kk < 64; kk += 4) {
        int kr = kb + kk - kr0;
        s_w[kk][d] = (kr >= 0 && kr < len) ? W[(size_t)kr * 64 + d] : 0.f;
    }
    __syncthreads();

    float res[16] = {};
    #pragma unroll 4
    for (int j = 0; j < 64; ++j) {
        float a = s_iw[j][d];
        #pragma unroll
        for (int i = 0; i < 16; ++i) res[i] += s_w[q + 4 * i][j] * a;
    }
    __syncthreads();
    #pragma unroll
    for (int i = 0; i < 16; ++i) s_w[q + 4 * i][d] = res[i];
    __syncthreads();

    for (int j = tid; j < 2048; j += 256) {
        int dd = j >> 5, w = j & 31;
        __nv_bfloat162 h = __floats2bfloat162_rn(s_w[2 * w][dd], s_w[2 * w + 1][dd]);
        *(uint32_t*)&g_WT[(size_t)dd * KT2 + kb + 2 * w] = *(uint32_t*)&h;
    }
}

// ---------------------------------------------------------------------------
// K0b: fold user-side tables + rate table.
// ---------------------------------------------------------------------------
__global__ void __launch_bounds__(256) k0_user(
    const float* __restrict__ gender_tab, const float* __restrict__ age_tab,
    const float* __restrict__ occ_tab, const float* __restrict__ area_tab,
    const float* __restrict__ user_W, const float* __restrict__ rate_tab,
    const float* __restrict__ item_W)
{
    __shared__ float s_W[64][65];
    __shared__ float s_T[32][65];
    int tid = threadIdx.x, d = tid & 63, q = tid >> 6;
    int rb = blockIdx.x * 32;

    #pragma unroll
    for (int j = q; j < 64; j += 4) s_W[j][d] = user_W[(192 + j) * 64 + d];

    for (int j2 = tid; j2 < 32 * 64; j2 += 256) {
        int rr = j2 >> 6, col = j2 & 63, r = rb + rr;
        float v = 0.f;
        if (r < 98)         v = gender_tab[r * 64 + col];
        else if (r < 105)   v = age_tab[(r - 98) * 64 + col];
        else if (r < 126)   v = occ_tab[(r - 105) * 64 + col];
        else if (r < 3528)  v = area_tab[(size_t)(r - 126) * 64 + col];
        else if (r < 3534)  v = rate_tab[(r - 3528) * 64 + col];
        s_T[rr][col] = v;
    }
    __syncthreads();

    for (int rr = q; rr < 32; rr += 4) {
        int r = rb + rr;
        if (r >= 3534) continue;
        float v = 0.f;
        if (r >= 126 && r < 3528) {
            #pragma unroll 16
            for (int j = 0; j < 64; ++j) v += s_T[rr][j] * s_W[j][d];
        } else {
            const float* Wg = (r < 98) ? user_W : (r < 105) ? (user_W + 64 * 64)
                            : (r < 126) ? (user_W + 128 * 64) : item_W;
            #pragma unroll 16
            for (int j = 0; j < 64; ++j) v += s_T[rr][j] * Wg[j * 64 + d];
        }
        if (r < 3528) g_UF[(size_t)r * 64 + d] = v;
        else          g_RF[(r - 3528) * 64 + d] = v;
    }
}

// ---------------------------------------------------------------------------
// K1: HBM-bound bits GEMM.
//   Raw int32 A goes global->smem via cp.async (4-deep ring, 32KB/stage) for
//   ~128KB in-flight per SM. Per-thread LDS of fragment int2s + bit-select
//   convert to bf16 registers (no bf16 smem stage, no A ldmatrix).
//   B: bf16 WT tiles via cp.async, 4-deep ring, plain ldmatrix.
//   Warp tile m16 x n32 (4 m-tiles x 2 n-halves). One combined commit group
//   per step; wait_group 2.
//   Steps: 0 genre (load cols [0,128), shift 1), 1..18 director (cols
//   base=24+128(s-1), shift 2), 19..81 actor (base=2212+128(s-19), aligned).
//   Splits (7): [0,10) [10,19) [19,32) [32,45) [45,58) [58,70) [70,82)
//   -> slots: sp0: 0 (genre) + 1 (director head); sp1: 2; sp2..sp6: 3..7
// ---------------------------------------------------------------------------
__device__ __forceinline__ void cp16(uint32_t dst, const void* src) {
    asm volatile("cp.async.cg.shared.global [%0], [%1], 16;\n" :: "r"(dst), "l"(src));
}
__device__ __forceinline__ void cp8(uint32_t dst, const void* src) {
    asm volatile("cp.async.ca.shared.global [%0], [%1], 8;\n" :: "r"(dst), "l"(src));
}
__device__ __forceinline__ int2 lds64(uint32_t a) {
    int2 v;
    asm volatile("ld.shared.v2.u32 {%0,%1}, [%2];\n" : "=r"(v.x), "=r"(v.y) : "r"(a));
    return v;
}
__device__ __forceinline__ void ldsm4(uint32_t& r0, uint32_t& r1, uint32_t& r2, uint32_t& r3,
                                      uint32_t addr) {
    asm volatile("ldmatrix.sync.aligned.m8n8.x4.shared.b16 {%0,%1,%2,%3}, [%4];\n"
                 : "=r"(r0), "=r"(r1), "=r"(r2), "=r"(r3) : "r"(addr));
}
__device__ __forceinline__ uint32_t cvt2(int2 v) {
    return (v.x ? 0x3F80u : 0u) | (v.y ? 0x3F800000u : 0u);
}

__device__ __forceinline__ int stepbase(int s) {
    return (s == 0) ? 0 : (s < 19 ? 24 + (s - 1) * 128 : 2212 + (s - 19) * 128);
}

__device__ __forceinline__ void issueA(const int* __restrict__ item, int rt, int s,
                                       int tid, uint32_t abuf)
{
    int base = stepbase(s);
    const char* src = (const char*)(item + (long)rt * 64 * ITEMW + base);
    if (s != 81) {
        #pragma unroll
        for (int i = 0; i < 16; ++i) {
            int c = i * 256 + tid;
            int row = c >> 6, w = c & 63;
            cp8(abuf + row * AST + w * 8, src + (long)row * (ITEMW * 4) + w * 8);
        }
    } else {
        // last actor step: cols [10148,10242) valid = 47 8-byte chunks; zero rest
        #pragma unroll
        for (int i = 0; i < 16; ++i) {
            int c = i * 256 + tid;
            int row = c >> 6, w = c & 63;
            uint32_t dst = abuf + row * AST + w * 8;
            if (w < 47) cp8(dst, src + (long)row * (ITEMW * 4) + w * 8);
            else asm volatile("st.shared.v2.u32 [%0], {%1,%1};\n" :: "r"(dst), "r"(0));
        }
    }
}

__device__ __forceinline__ void issueB(int s, int tid, uint32_t bbuf)
{
    const char* wt = (const char*)g_WT + (size_t)s * 256;
    #pragma unroll
    for (int it = 0; it < 4; ++it) {
        int j = it * 256 + tid;
        int dd = j >> 4, w16 = j & 15;
        cp16(bbuf + dd * BSTR + w16 * 16, wt + (size_t)dd * (KT2 * 2) + w16 * 16);
    }
}

__device__ __forceinline__ void flushAC(float (&acc)[4][4], int& cr, int& cr8, int slot,
                                        int rt, int lane, int wm, int wg)
{
    int row = rt * 64 + wm * 16 + (lane >> 2);
    int tg2 = 2 * (lane & 3);
    float* b0 = g_part + ((size_t)slot * BSZ + row) * PCX;
    float* b8 = b0 + 8 * PCX;
    #pragma unroll
    for (int li = 0; li < 4; ++li) {
        int col = (4 * wg + li) * 8 + tg2;
        b0[col] = acc[li][0]; b0[col + 1] = acc[li][1];
        b8[col] = acc[li][2]; b8[col + 1] = acc[li][3];
        acc[li][0] = acc[li][1] = acc[li][2] = acc[li][3] = 0.f;
    }
    if (wg == 0) {
        int c1 = cr, c2 = cr8;
        c1 += __shfl_xor_sync(0xffffffffu, c1, 1);
        c1 += __shfl_xor_sync(0xffffffffu, c1, 2);
        c2 += __shfl_xor_sync(0xffffffffu, c2, 1);
        c2 += __shfl_xor_sync(0xffffffffu, c2, 2);
        if ((lane & 3) == 0) {
            g_cnt[slot * BSZ + row]     = (float)c1;
            g_cnt[slot * BSZ + row + 8] = (float)c2;
        }
    }
    cr = 0; cr8 = 0;
}

__global__ void __launch_bounds__(256) k1_gemm(const int* __restrict__ item)
{
    extern __shared__ __align__(16) uint8_t smem[];
    uint32_t sA = (uint32_t)__cvta_generic_to_shared(smem);
    uint32_t sB = sA + 4 * ATILE;

    int tid = threadIdx.x, lane = tid & 31, w = tid >> 5;
    int wm = w & 3, wg = w >> 2;     // 4 m-tiles x 2 n-halves
    int rt = blockIdx.x, sp = blockIdx.y;
    int s0, s1;
    switch (sp) {
        case 0: s0 = 0;  s1 = 10; break;
        case 1: s0 = 10; s1 = 19; break;
        case 2: s0 = 19; s1 = 32; break;
        case 3: s0 = 32; s1 = 45; break;
        case 4: s0 = 45; s1 = 58; break;
        case 5: s0 = 58; s1 = 70; break;
        default: s0 = 70; s1 = 82; break;
    }

    // per-thread fragment offsets
    int qj = lane & 3;
    int r0l = wm * 16 + (lane >> 2);            // local A row for a0/a2
    uint32_t aoff0 = r0l * AST + qj * 8;        // (row, col 2*qj)
    uint32_t aoff8 = (r0l + 8) * AST + qj * 8;
    int tsel = (lane >> 4) & 1;
    int col8 = ((lane >> 3) & 1) * 16;
    uint32_t boff0 = (uint32_t)(((4 * wg + tsel) * 8 + (lane & 7)) * BSTR + col8);
    uint32_t boff1 = (uint32_t)(((4 * wg + 2 + tsel) * 8 + (lane & 7)) * BSTR + col8);

    float acc[4][4] = {};
    int cnt_r = 0, cnt_r8 = 0;

    // prologue: 3 combined groups in flight
    #pragma unroll
    for (int i = 0; i < 3; ++i) {
        issueA(item, rt, s0 + i, tid, sA + ((s0 + i) & 3) * ATILE);
        issueB(s0 + i, tid, sB + ((s0 + i) & 3) * BTILE);
        asm volatile("cp.async.commit_group;\n" ::: "memory");
    }

    for (int s = s0; s < s1; ++s) {
        asm volatile("cp.async.wait_group 2;\n" ::: "memory");
        __syncthreads();
        if (s + 3 < s1) {
            issueA(item, rt, s + 3, tid, sA + ((s + 3) & 3) * ATILE);
            issueB(s + 3, tid, sB + ((s + 3) & 3) * BTILE);
            asm volatile("cp.async.commit_group;\n" ::: "memory");
        }
        uint32_t ab = sA + (s & 3) * ATILE;
        uint32_t bb = sB + (s & 3) * BTILE;
        int base = stepbase(s);
        bool masked = (s < 2) || (s == 18);
        int lo = (s == 0) ? 1 : 26;              // only used when masked
        int hi = (s == 0) ? 26 : 2212;

        #pragma unroll
        for (int ks = 0; ks < 8; ++ks) {
            int2 x0 = lds64(ab + aoff0 + ks * 64);
            int2 x1 = lds64(ab + aoff8 + ks * 64);
            int2 x2 = lds64(ab + aoff0 + ks * 64 + 32);
            int2 x3 = lds64(ab + aoff8 + ks * 64 + 32);
            uint32_t a0 = cvt2(x0), a1 = cvt2(x1), a2 = cvt2(x2), a3 = cvt2(x3);
            if (wg == 0) {
                if (masked) {
                    int c0 = base + ks * 16 + 2 * qj;
                    int m0 = (c0 >= lo) & (c0 < hi);
                    int m1 = (c0 + 1 >= lo) & (c0 + 1 < hi);
                    int m8 = (c0 + 8 >= lo) & (c0 + 8 < hi);
                    int m9 = (c0 + 9 >= lo) & (c0 + 9 < hi);
                    cnt_r  += (m0 ? x0.x : 0) + (m1 ? x0.y : 0) + (m8 ? x2.x : 0) + (m9 ? x2.y : 0);
                    cnt_r8 += (m0 ? x1.x : 0) + (m1 ? x1.y : 0) + (m8 ? x3.x : 0) + (m9 ? x3.y : 0);
                } else {
                    cnt_r  += x0.x + x0.y + x2.x + x2.y;
                    cnt_r8 += x1.x + x1.y + x3.x + x3.y;
                }
            }
            uint32_t p0, p1, p2, p3, q0, q1, q2, q3;
            ldsm4(p0, p1, p2, p3, bb + boff0 + ks * 32);
            ldsm4(q0, q1, q2, q3, bb + boff1 + ks * 32);
            #define HM(ACC, B0, B1)                                               \
                asm volatile(                                                     \
                    "mma.sync.aligned.m16n8k16.row.col.f32.bf16.bf16.f32 "        \
                    "{%0,%1,%2,%3}, {%4,%5,%6,%7}, {%8,%9}, {%0,%1,%2,%3};\n"     \
                    : "+f"(ACC[0]), "+f"(ACC[1]), "+f"(ACC[2]), "+f"(ACC[3])      \
                    : "r"(a0), "r"(a1), "r"(a2), "r"(a3), "r"(B0), "r"(B1))
            HM(acc[0], p0, p1);
            HM(acc[1], p2, p3);
            HM(acc[2], q0, q1);
            HM(acc[3], q2, q3);
            #undef HM
        }
        if (sp == 0 && s == 0) flushAC(acc, cnt_r, cnt_r8, 0, rt, lane, wm, wg);
    }
    flushAC(acc, cnt_r, cnt_r8, (sp == 0) ? 1 : sp + 1, rt, lane, wm, wg);
}

// ---------------------------------------------------------------------------
// K2: reduce partial slots, finalize x / y / edge, per-row scalars,
// s-vector partials. 4 rows per CTA, 1024 CTAs.
// ---------------------------------------------------------------------------
__global__ void __launch_bounds__(256) k2_finalize(
    const int* __restrict__ user_emb, const int* __restrict__ item,
    const int* __restrict__ edge_emb,
    const float* __restrict__ user_b, const float* __restrict__ item_b,
    const float* __restrict__ edges_tab,
    const float* __restrict__ uu_w, const float* __restrict__ ui_w,
    const float* __restrict__ iu_w, const float* __restrict__ ii_w)
{
    int tid = threadIdx.x, lane = tid & 31, warp = tid >> 5;
    int rr = tid >> 6, d = tid & 63;
    int row = blockIdx.x * 4 + rr;

    float ng = g_part[((size_t)0 * BSZ + row) * PCX + d];
    float nd = g_part[((size_t)1 * BSZ + row) * PCX + d]
             + g_part[((size_t)2 * BSZ + row) * PCX + d];
    float na = 0.f, ca = 0.f;
    #pragma unroll
    for (int t = 3; t < 8; ++t) {
        na += g_part[((size_t)t * BSZ + row) * PCX + d];
        ca += g_cnt[t * BSZ + row];
    }
    float cg = g_cnt[0 * BSZ + row];
    float cd = g_cnt[1 * BSZ + row] + g_cnt[2 * BSZ + row];

    int ri = item[(long)row * ITEMW];
    float y = (g_RF[ri * 64 + d] + ng / cg + nd / cd + na / ca + item_b[d]) * 0.12f;

    int gi = user_emb[row * 4 + 0], ai = user_emb[row * 4 + 1];
    int oi = user_emb[row * 4 + 2], ari = user_emb[row * 4 + 3];
    float x = (g_UF[gi * 64 + d] + g_UF[(98 + ai) * 64 + d] + g_UF[(105 + oi) * 64 + d]
             + g_UF[(size_t)(126 + ari) * 64 + d] + user_b[d]) * 0.12f;
    float e = edges_tab[edge_emb[row] * 64 + d] * 0.12f;

    g_X[row * 64 + d] = x;
    g_Y[row * 64 + d] = y;

    __shared__ float sx[4][64], sy[4][64];
    __shared__ float red[8][6], srow[4][6];
    sx[rr][d] = x; sy[rr][d] = y;

    float xe = x * e, ye = y * e;
    float pr[6] = { xe * uu_w[d], xe * ui_w[d], ye * ui_w[d],
                    ye * ii_w[d], ye * iu_w[d], xe * iu_w[d] };
    #pragma unroll
    for (int o = 16; o; o >>= 1) {
        #pragma unroll
        for (int j = 0; j < 6; ++j) pr[j] += __shfl_xor_sync(0xffffffffu, pr[j], o);
    }
    if (lane == 0) {
        #pragma unroll
        for (int j = 0; j < 6; ++j) red[warp][j] = pr[j];
    }
    __syncthreads();
    if (tid < 24) {
        int r2 = tid / 6, j = tid % 6;
        float v = red[2 * r2][j] + red[2 * r2 + 1][j];
        srow[r2][j] = v;
        g_S[(size_t)(blockIdx.x * 4 + r2) * 8 + j] = v;
    }
    __syncthreads();
    if (tid < 64) {
        float s1 = 0, s2 = 0, s3 = 0, s4 = 0;
        #pragma unroll
        for (int r2 = 0; r2 < 4; ++r2) {
            float xv = sx[r2][tid], yv = sy[r2][tid];
            s1 += srow[r2][0] * xv;   // x_xx * x
            s2 += srow[r2][2] * yv;   // x_xy_y * y
            s3 += srow[r2][3] * yv;   // y_yy * y
            s4 += srow[r2][5] * xv;   // y_yx_x * x
        }
        g_SP[(0 * 1024 + blockIdx.x) * 64 + tid] = s1;
        g_SP[(1 * 1024 + blockIdx.x) * 64 + tid] = s2;
        g_SP[(2 * 1024 + blockIdx.x) * 64 + tid] = s3;
        g_SP[(3 * 1024 + blockIdx.x) * 64 + tid] = s4;
    }
}

// ---------------------------------------------------------------------------
// K3a: reduce 1024 s-vector partials to 16 (parallel over 16 CTAs)
// ---------------------------------------------------------------------------
__global__ void __launch_bounds__(256) k3a_reduce()
{
    int tid = threadIdx.x, v = tid >> 6, d = tid & 63, b = blockIdx.x;
    float s = 0.f;
    #pragma unroll 8
    for (int i = b * 64; i < b * 64 + 64; ++i)
        s += g_SP[((size_t)v * 1024 + i) * 64 + d];
    g_SP2[(v * 16 + b) * 64 + d] = s;
}

// ---------------------------------------------------------------------------
// K3b: final reduce + u1..u4 matvecs + edge branch
// ---------------------------------------------------------------------------
__global__ void __launch_bounds__(320) k3b_final(
    const float* __restrict__ uu_W1, const float* __restrict__ ui_W1,
    const float* __restrict__ ii_W1, const float* __restrict__ iu_W1,
    const float* __restrict__ edge_W, const float* __restrict__ edges_tab)
{
    __shared__ float sq[4][64];
    __shared__ float ev[64];
    int tid = threadIdx.x;
    if (tid < 256) {
        int v = tid >> 6, d = tid & 63;
        float tot = 0.f;
        #pragma unroll
        for (int b = 0; b < 16; ++b) tot += g_SP2[(v * 16 + b) * 64 + d];
        sq[v][d] = tot;
    } else {
        ev[tid - 256] = edges_tab[tid - 256] * 0.12f;
    }
    __syncthreads();
    if (tid < 256) {
        int v = tid >> 6, d = tid & 63;
        const float* W1 = (v == 0) ? uu_W1 : (v == 1) ? ui_W1 : (v == 2) ? ii_W1 : iu_W1;
        float u = 0.f;
        #pragma unroll
        for (int j = 0; j < 64; ++j) u += sq[v][j] * W1[j * 64 + d];
        g_U[v * 64 + d] = u;
    } else {
        int dd = tid - 256;
        float nv = 0.f;
        #pragma unroll
        for (int j = 0; j < 64; ++j) nv += ev[j] * edge_W[j * 64 + dd];
        nv = nv >= 0.f ? nv : 0.01f * nv;
        g_O3[dd] = 0.5f * (nv + ev[dd]);
    }
}

// ---------------------------------------------------------------------------
// K4: final elementwise assembly of the three outputs
// ---------------------------------------------------------------------------
__global__ void __launch_bounds__(256) k4_out(float* __restrict__ out)
{
    int idx = blockIdx.x * 256 + threadIdx.x;   // 0..262143
    int r = idx >> 6, d = idx & 63;
    float x_xx   = g_S[(size_t)r * 8 + 0];
    float x_xy_x = g_S[(size_t)r * 8 + 1];
    float y_yy   = g_S[(size_t)r * 8 + 3];
    float y_yx_y = g_S[(size_t)r * 8 + 4];
    float a1 = x_xx * g_U[d];         a1 = a1 >= 0.f ? a1 : 0.01f * a1;
    float a2 = x_xy_x * g_U[64 + d];  a2 = a2 >= 0.f ? a2 : 0.01f * a2;
    float b1 = y_yy * g_U[128 + d];   b1 = b1 >= 0.f ? b1 : 0.01f * b1;
    float b2 = y_yx_y * g_U[192 + d]; b2 = b2 >= 0.f ? b2 : 0.01f * b2;
    out[idx]          = ((a1 + a2) * 0.5f + g_X[idx]) * 0.5f;
    out[262144 + idx] = ((b1 + b2) * 0.5f + g_Y[idx]) * 0.5f;
    out[524288 + idx] = g_O3[d];
}

// ---------------------------------------------------------------------------
// launch
// ---------------------------------------------------------------------------
extern "C" void kernel_launch(void* const* d_in, const int* in_sizes, int n_in,
                              void* d_out, int out_size)
{
    const int*   user_emb   = (const int*)d_in[0];
    const int*   item_emb   = (const int*)d_in[1];
    const int*   edge_emb   = (const int*)d_in[2];
    const float* gender_tab = (const float*)d_in[3];
    const float* age_tab    = (const float*)d_in[4];
    const float* occ_tab    = (const float*)d_in[5];
    const float* area_tab   = (const float*)d_in[6];
    const float* user_W     = (const float*)d_in[7];
    const float* user_b     = (const float*)d_in[8];
    const float* rate_tab   = (const float*)d_in[9];
    const float* genre_W    = (const float*)d_in[10];
    const float* director_W = (const float*)d_in[11];
    const float* actor_W    = (const float*)d_in[12];
    const float* item_W     = (const float*)d_in[13];
    const float* item_b     = (const float*)d_in[14];
    const float* edges_tab  = (const float*)d_in[15];
    const float* uu_w       = (const float*)d_in[16];
    const float* ui_w       = (const float*)d_in[17];
    const float* iu_w       = (const float*)d_in[18];
    const float* ii_w       = (const float*)d_in[19];
    const float* edge_W     = (const float*)d_in[20];
    const float* uu_W1      = (const float*)d_in[21];
    const float* ui_W1      = (const float*)d_in[22];
    const float* iu_W1      = (const float*)d_in[23];
    const float* ii_W1      = (const float*)d_in[24];
    float* out = (float*)d_out;

    cudaFuncSetAttribute(k1_gemm, cudaFuncAttributeMaxDynamicSharedMemorySize, K1SMEM);

    k_dummy<<<1, 1>>>();
    k0_wt<<<164, 256>>>(genre_W, director_W, actor_W, item_W);
    k0_user<<<111, 256>>>(gender_tab, age_tab, occ_tab, area_tab, user_W, rate_tab, item_W);
    k1_gemm<<<dim3(64, 7), 256, K1SMEM>>>(item_emb);
    k2_finalize<<<1024, 256>>>(user_emb, item_emb, edge_emb, user_b, item_b, edges_tab,
                               uu_w, ui_w, iu_w, ii_w);
    k3a_reduce<<<16, 256>>>();
    k3b_final<<<1, 320>>>(uu_W1, ui_W1, ii_W1, iu_W1, edge_W, edges_tab);
    k4_out<<<1024, 256>>>(out);
}

// round 12
// speedup vs baseline: 1.3580x; 1.3580x over previous
#include <cuda_runtime.h>
#include <cuda_bf16.h>
#include <cstdint>

// ---------------------------------------------------------------------------
// Problem constants
// ---------------------------------------------------------------------------
#define BSZ    4096
#define ITEMW  10242
#define KT2    10496      // padded K: 128 (genre) + 2304 (director) + 8064 (actor)
#define NSLOT  10         // 0=genre, 1-2=director, 3-9=actor
#define PCX    64         // numerator columns per slot
#define BSTR   272        // B row stride bytes (128 bf16 + 16 pad)
#define BTILE  (64 * BSTR)    // 17408 B per B stage
#define K1SMEM (3 * BTILE)    // 52224 B (B ring only; A never staged)

// ---------------------------------------------------------------------------
// Device scratch (static globals; no allocations anywhere)
// ---------------------------------------------------------------------------
__device__ __align__(16) __nv_bfloat16 g_WT[64 * KT2];      // fused weights [d][k], shifts baked
__device__ float g_UF[3528 * 64];                            // user folds
__device__ float g_RF[6 * 64];                               // rate_tab @ item_W[0:64]
__device__ float g_part[(size_t)NSLOT * BSZ * PCX];          // GEMM partial numerators
__device__ float g_cnt[NSLOT * BSZ];                         // per-field bit counts
__device__ float g_X[BSZ * 64], g_Y[BSZ * 64];               // x, y vectors
__device__ float g_S[BSZ * 8];                               // per-row scalars (6 used)
__device__ float g_SP[4 * 1024 * 64];                        // per-CTA partials of s1..s4
__device__ float g_SP2[4 * 16 * 64];                         // stage-2 partials
__device__ float g_U[4 * 64];                                // u1..u4
__device__ float g_O3[64];                                   // edge-branch output row
__device__ int   g_dummy[1];

// ---------------------------------------------------------------------------
// Dummy kernel: keeps ncu's capture slot on k1_gemm (k1 must be 4th launch).
// ---------------------------------------------------------------------------
__global__ void k_dummy() { g_dummy[0] = 1; }

// ---------------------------------------------------------------------------
// K0a: fold item-side weights into g_WT (bf16), shifts baked:
//   genre   k [0,128):    bit kr = k - 1     (loads at item col k)
//   director k [128,2432): bit kr = k - 130   (loads at item col k - 104)
//   actor   k [2432,10496): bit kr = k - 2432 (loads at item col k - 220)
// Out-of-range kr -> weight 0 (absorbs garbage bits from shifted loads).
// ---------------------------------------------------------------------------
__global__ void __launch_bounds__(256) k0_wt(
    const float* __restrict__ genre_W, const float* __restrict__ director_W,
    const float* __restrict__ actor_W, const float* __restrict__ item_W)
{
    __shared__ float s_iw[64][65];
    __shared__ float s_w[64][65];
    int tid = threadIdx.x, d = tid & 63, q = tid >> 6;
    int blk = blockIdx.x;           // 0..163
    int kb = blk * 64;
    const float* W; int len, iwo, kr0;
    if (blk < 2)       { W = genre_W;    len = 25;   iwo = 64;  kr0 = 1;    }
    else if (blk < 38) { W = director_W; len = 2186; iwo = 128; kr0 = 130;  }
    else               { W = actor_W;    len = 8030; iwo = 192; kr0 = 2432; }

    #pragma unroll
    for (int j = q; j < 64; j += 4) s_iw[j][d] = item_W[(iwo + j) * 64 + d];
    #pragma unroll
    for (int kk = q; kk < 64; kk += 4) {
        int kr = kb + kk - kr0;
        s_w[kk][d] = (kr >= 0 && kr < len) ? W[(size_t)kr * 64 + d] : 0.f;
    }
    __syncthreads();

    float res[16] = {};
    #pragma unroll 4
    for (int j = 0; j < 64; ++j) {
        float a = s_iw[j][d];
        #pragma unroll
        for (int i = 0; i < 16; ++i) res[i] += s_w[q + 4 * i][j] * a;
    }
    __syncthreads();
    #pragma unroll
    for (int i = 0; i < 16; ++i) s_w[q + 4 * i][d] = res[i];
    __syncthreads();

    for (int j = tid; j < 2048; j += 256) {
        int dd = j >> 5, w = j & 31;
        __nv_bfloat162 h = __floats2bfloat162_rn(s_w[2 * w][dd], s_w[2 * w + 1][dd]);
        *(uint32_t*)&g_WT[(size_t)dd * KT2 + kb + 2 * w] = *(uint32_t*)&h;
    }
}

// ---------------------------------------------------------------------------
// K0b: fold user-side tables + rate table.
// ---------------------------------------------------------------------------
__global__ void __launch_bounds__(256) k0_user(
    const float* __restrict__ gender_tab, const float* __restrict__ age_tab,
    const float* __restrict__ occ_tab, const float* __restrict__ area_tab,
    const float* __restrict__ user_W, const float* __restrict__ rate_tab,
    const float* __restrict__ item_W)
{
    __shared__ float s_W[64][65];
    __shared__ float s_T[32][65];
    int tid = threadIdx.x, d = tid & 63, q = tid >> 6;
    int rb = blockIdx.x * 32;

    #pragma unroll
    for (int j = q; j < 64; j += 4) s_W[j][d] = user_W[(192 + j) * 64 + d];

    for (int j2 = tid; j2 < 32 * 64; j2 += 256) {
        int rr = j2 >> 6, col = j2 & 63, r = rb + rr;
        float v = 0.f;
        if (r < 98)         v = gender_tab[r * 64 + col];
        else if (r < 105)   v = age_tab[(r - 98) * 64 + col];
        else if (r < 126)   v = occ_tab[(r - 105) * 64 + col];
        else if (r < 3528)  v = area_tab[(size_t)(r - 126) * 64 + col];
        else if (r < 3534)  v = rate_tab[(r - 3528) * 64 + col];
        s_T[rr][col] = v;
    }
    __syncthreads();

    for (int rr = q; rr < 32; rr += 4) {
        int r = rb + rr;
        if (r >= 3534) continue;
        float v = 0.f;
        if (r >= 126 && r < 3528) {
            #pragma unroll 16
            for (int j = 0; j < 64; ++j) v += s_T[rr][j] * s_W[j][d];
        } else {
            const float* Wg = (r < 98) ? user_W : (r < 105) ? (user_W + 64 * 64)
                            : (r < 126) ? (user_W + 128 * 64) : item_W;
            #pragma unroll 16
            for (int j = 0; j < 64; ++j) v += s_T[rr][j] * Wg[j * 64 + d];
        }
        if (r < 3528) g_UF[(size_t)r * 64 + d] = v;
        else          g_RF[(r - 3528) * 64 + d] = v;
    }
}

// ---------------------------------------------------------------------------
// K1: HBM-bound bits GEMM.
//   M=128 tile, 8 warps each m16 x n64 -> A fragments are warp-private and
//   loaded global->register directly in mma layout (int2 pairs), quarter-step
//   (32-col) double-buffered prefetch. No A smem, no A sync.
//   B: bf16 WT tiles via cp.async 3-ring (one commit/step, wait_group 1).
//   Counts from prefetch regs (masked only on steps 0,1,18).
//   Steps (K=128 each): 0 genre (cols [0,128)), 1..18 director
//   (base 24+128(s-1)), 19..81 actor (base 2212+128(s-19)).
//   Grid 32 row-tiles x 9 splits = 288 CTAs = one wave at 2 CTAs/SM.
//   Splits: sp0 [0,10) slots 0,1; sp1 [10,19) slot 2;
//           sp2..sp8 [19+9i, 28+9i) slots 3..9.
// ---------------------------------------------------------------------------
__device__ __forceinline__ void cp16(uint32_t dst, const void* src) {
    asm volatile("cp.async.cg.shared.global [%0], [%1], 16;\n" :: "r"(dst), "l"(src));
}
__device__ __forceinline__ void ldsm4(uint32_t& r0, uint32_t& r1, uint32_t& r2, uint32_t& r3,
                                      uint32_t addr) {
    asm volatile("ldmatrix.sync.aligned.m8n8.x4.shared.b16 {%0,%1,%2,%3}, [%4];\n"
                 : "=r"(r0), "=r"(r1), "=r"(r2), "=r"(r3) : "r"(addr));
}
__device__ __forceinline__ uint32_t cvt2(int2 v) {
    return (v.x ? 0x3F80u : 0u) | (v.y ? 0x3F800000u : 0u);
}
__device__ __forceinline__ int stepbase(int s) {
    return (s == 0) ? 0 : (s < 19 ? 24 + (s - 1) * 128 : 2212 + (s - 19) * 128);
}

__device__ __forceinline__ void issueB(int s, int tid, uint32_t bbuf)
{
    const char* wt = (const char*)g_WT + (size_t)s * 256;
    #pragma unroll
    for (int it = 0; it < 4; ++it) {
        int j = it * 256 + tid;
        int dd = j >> 4, w16 = j & 15;
        cp16(bbuf + dd * BSTR + w16 * 16, wt + (size_t)dd * (KT2 * 2) + w16 * 16);
    }
    asm volatile("cp.async.commit_group;\n" ::: "memory");
}

// load one quarter (32 cols) of A fragments: 8 int2 per thread
__device__ __forceinline__ void loadA(const int* __restrict__ p0, const int* __restrict__ p1,
                                      int cq, bool guard, int2 (&B)[8])
{
    #pragma unroll
    for (int kl = 0; kl < 2; ++kl) {
        int c = cq + kl * 16;
        if (!guard) {
            B[kl * 4 + 0] = *(const int2*)(p0 + c);
            B[kl * 4 + 1] = *(const int2*)(p1 + c);
            B[kl * 4 + 2] = *(const int2*)(p0 + c + 8);
            B[kl * 4 + 3] = *(const int2*)(p1 + c + 8);
        } else {
            int2 z = make_int2(0, 0);
            B[kl * 4 + 0] = (c < ITEMW)     ? *(const int2*)(p0 + c)     : z;
            B[kl * 4 + 1] = (c < ITEMW)     ? *(const int2*)(p1 + c)     : z;
            B[kl * 4 + 2] = (c + 8 < ITEMW) ? *(const int2*)(p0 + c + 8) : z;
            B[kl * 4 + 3] = (c + 8 < ITEMW) ? *(const int2*)(p1 + c + 8) : z;
        }
    }
}

// consume one quarter: 2 k-steps of mma over n=64, plus counts
__device__ __forceinline__ void consume(const int2 (&Bf)[8], uint32_t bb, uint32_t boff0,
                                        int q, int cq, bool masked, int lo, int hi,
                                        float (&acc)[8][4], int& cnt0, int& cnt8)
{
    #pragma unroll
    for (int kl = 0; kl < 2; ++kl) {
        int2 x0 = Bf[kl * 4 + 0], x1 = Bf[kl * 4 + 1];
        int2 x2 = Bf[kl * 4 + 2], x3 = Bf[kl * 4 + 3];
        uint32_t a0 = cvt2(x0), a1 = cvt2(x1), a2 = cvt2(x2), a3 = cvt2(x3);
        if (masked) {
            int c = cq + kl * 16;
            int m0 = (c     >= lo) & (c     < hi);
            int m1 = (c + 1 >= lo) & (c + 1 < hi);
            int m8 = (c + 8 >= lo) & (c + 8 < hi);
            int m9 = (c + 9 >= lo) & (c + 9 < hi);
            cnt0 += (m0 ? x0.x : 0) + (m1 ? x0.y : 0) + (m8 ? x2.x : 0) + (m9 ? x2.y : 0);
            cnt8 += (m0 ? x1.x : 0) + (m1 ? x1.y : 0) + (m8 ? x3.x : 0) + (m9 ? x3.y : 0);
        } else {
            cnt0 += x0.x + x0.y + x2.x + x2.y;
            cnt8 += x1.x + x1.y + x3.x + x3.y;
        }
        uint32_t koff = (uint32_t)((q * 2 + kl) * 32);
        #pragma unroll
        for (int j = 0; j < 4; ++j) {
            uint32_t p0r, p1r, p2r, p3r;
            ldsm4(p0r, p1r, p2r, p3r, bb + boff0 + (uint32_t)(j * 16 * BSTR) + koff);
            #define HM(ACC, B0, B1)                                               \
                asm volatile(                                                     \
                    "mma.sync.aligned.m16n8k16.row.col.f32.bf16.bf16.f32 "        \
                    "{%0,%1,%2,%3}, {%4,%5,%6,%7}, {%8,%9}, {%0,%1,%2,%3};\n"     \
                    : "+f"(ACC[0]), "+f"(ACC[1]), "+f"(ACC[2]), "+f"(ACC[3])      \
                    : "r"(a0), "r"(a1), "r"(a2), "r"(a3), "r"(B0), "r"(B1))
            HM(acc[2 * j],     p0r, p1r);
            HM(acc[2 * j + 1], p2r, p3r);
            #undef HM
        }
    }
}

__device__ __forceinline__ void flushAC(float (&acc)[8][4], int& c0, int& c8, int slot,
                                        int rt, int lane, int w)
{
    int row = rt * 128 + w * 16 + (lane >> 2);
    int tg2 = 2 * (lane & 3);
    float* b0 = g_part + ((size_t)slot * BSZ + row) * PCX;
    float* b8 = b0 + 8 * PCX;
    #pragma unroll
    for (int t = 0; t < 8; ++t) {
        int col = t * 8 + tg2;
        *(float2*)&b0[col] = make_float2(acc[t][0], acc[t][1]);
        *(float2*)&b8[col] = make_float2(acc[t][2], acc[t][3]);
        acc[t][0] = acc[t][1] = acc[t][2] = acc[t][3] = 0.f;
    }
    int s1 = c0, s2 = c8;
    s1 += __shfl_xor_sync(0xffffffffu, s1, 1);
    s1 += __shfl_xor_sync(0xffffffffu, s1, 2);
    s2 += __shfl_xor_sync(0xffffffffu, s2, 1);
    s2 += __shfl_xor_sync(0xffffffffu, s2, 2);
    if ((lane & 3) == 0) {
        g_cnt[slot * BSZ + row]     = (float)s1;
        g_cnt[slot * BSZ + row + 8] = (float)s2;
    }
    c0 = 0; c8 = 0;
}

__global__ void __launch_bounds__(256, 2) k1_gemm(const int* __restrict__ item)
{
    extern __shared__ __align__(16) uint8_t smem[];
    uint32_t sB = (uint32_t)__cvta_generic_to_shared(smem);

    int tid = threadIdx.x, lane = tid & 31, w = tid >> 5;
    int rt = blockIdx.x, sp = blockIdx.y;
    int s0, s1;
    if (sp == 0)      { s0 = 0;  s1 = 10; }
    else if (sp == 1) { s0 = 10; s1 = 19; }
    else              { s0 = 19 + 9 * (sp - 2); s1 = s0 + 9; }

    int qj2 = 2 * (lane & 3);
    long row0 = (long)(rt * 128 + w * 16 + (lane >> 2));
    const int* p0 = item + row0 * ITEMW;
    const int* p1 = p0 + (long)8 * ITEMW;
    int tsel = (lane >> 4) & 1;
    int col8 = ((lane >> 3) & 1) * 16;
    uint32_t boff0 = (uint32_t)((tsel * 8 + (lane & 7)) * BSTR + col8);

    float acc[8][4] = {};
    int cnt0 = 0, cnt8 = 0;
    int2 buf[2][8];

    issueB(s0,     tid, sB + (s0 % 3) * BTILE);
    issueB(s0 + 1, tid, sB + ((s0 + 1) % 3) * BTILE);
    loadA(p0, p1, stepbase(s0) + qj2, false, buf[0]);   // s0 is never 81

    for (int s = s0; s < s1; ++s) {
        if (s + 1 < s1) { asm volatile("cp.async.wait_group 1;\n" ::: "memory"); }
        else            { asm volatile("cp.async.wait_group 0;\n" ::: "memory"); }
        __syncthreads();
        if (s + 2 < s1) issueB(s + 2, tid, sB + ((s + 2) % 3) * BTILE);

        int base = stepbase(s);
        bool masked = (s <= 1) || (s == 18);
        int lo = (s == 0) ? 1 : 26;
        int hi = (s == 0) ? 26 : 2212;
        uint32_t bb = sB + (s % 3) * BTILE;

        #pragma unroll
        for (int q = 0; q < 4; ++q) {
            int ns = s, nq = q + 1;
            if (nq == 4) { nq = 0; ns = s + 1; }
            if (ns < s1)
                loadA(p0, p1, stepbase(ns) + nq * 32 + qj2, ns == 81, buf[(q + 1) & 1]);
            consume(buf[q & 1], bb, boff0, q, base + q * 32 + qj2,
                    masked, lo, hi, acc, cnt0, cnt8);
        }
        if (sp == 0 && s == 0) flushAC(acc, cnt0, cnt8, 0, rt, lane, w);   // genre
    }
    flushAC(acc, cnt0, cnt8, (sp == 0) ? 1 : sp + 1, rt, lane, w);
}

// ---------------------------------------------------------------------------
// K2: reduce partial slots, finalize x / y / edge, per-row scalars,
// s-vector partials. 4 rows per CTA, 1024 CTAs.
// ---------------------------------------------------------------------------
__global__ void __launch_bounds__(256) k2_finalize(
    const int* __restrict__ user_emb, const int* __restrict__ item,
    const int* __restrict__ edge_emb,
    const float* __restrict__ user_b, const float* __restrict__ item_b,
    const float* __restrict__ edges_tab,
    const float* __restrict__ uu_w, const float* __restrict__ ui_w,
    const float* __restrict__ iu_w, const float* __restrict__ ii_w)
{
    int tid = threadIdx.x, lane = tid & 31, warp = tid >> 5;
    int rr = tid >> 6, d = tid & 63;
    int row = blockIdx.x * 4 + rr;

    float ng = g_part[((size_t)0 * BSZ + row) * PCX + d];
    float nd = g_part[((size_t)1 * BSZ + row) * PCX + d]
             + g_part[((size_t)2 * BSZ + row) * PCX + d];
    float na = 0.f, ca = 0.f;
    #pragma unroll
    for (int t = 3; t < NSLOT; ++t) {
        na += g_part[((size_t)t * BSZ + row) * PCX + d];
        ca += g_cnt[t * BSZ + row];
    }
    float cg = g_cnt[0 * BSZ + row];
    float cd = g_cnt[1 * BSZ + row] + g_cnt[2 * BSZ + row];

    int ri = item[(long)row * ITEMW];
    float y = (g_RF[ri * 64 + d] + ng / cg + nd / cd + na / ca + item_b[d]) * 0.12f;

    int gi = user_emb[row * 4 + 0], ai = user_emb[row * 4 + 1];
    int oi = user_emb[row * 4 + 2], ari = user_emb[row * 4 + 3];
    float x = (g_UF[gi * 64 + d] + g_UF[(98 + ai) * 64 + d] + g_UF[(105 + oi) * 64 + d]
             + g_UF[(size_t)(126 + ari) * 64 + d] + user_b[d]) * 0.12f;
    float e = edges_tab[edge_emb[row] * 64 + d] * 0.12f;

    g_X[row * 64 + d] = x;
    g_Y[row * 64 + d] = y;

    __shared__ float sx[4][64], sy[4][64];
    __shared__ float red[8][6], srow[4][6];
    sx[rr][d] = x; sy[rr][d] = y;

    float xe = x * e, ye = y * e;
    float pr[6] = { xe * uu_w[d], xe * ui_w[d], ye * ui_w[d],
                    ye * ii_w[d], ye * iu_w[d], xe * iu_w[d] };
    #pragma unroll
    for (int o = 16; o; o >>= 1) {
        #pragma unroll
        for (int j = 0; j < 6; ++j) pr[j] += __shfl_xor_sync(0xffffffffu, pr[j], o);
    }
    if (lane == 0) {
        #pragma unroll
        for (int j = 0; j < 6; ++j) red[warp][j] = pr[j];
    }
    __syncthreads();
    if (tid < 24) {
        int r2 = tid / 6, j = tid % 6;
        float v = red[2 * r2][j] + red[2 * r2 + 1][j];
        srow[r2][j] = v;
        g_S[(size_t)(blockIdx.x * 4 + r2) * 8 + j] = v;
    }
    __syncthreads();
    if (tid < 64) {
        float s1 = 0, s2 = 0, s3 = 0, s4 = 0;
        #pragma unroll
        for (int r2 = 0; r2 < 4; ++r2) {
            float xv = sx[r2][tid], yv = sy[r2][tid];
            s1 += srow[r2][0] * xv;   // x_xx * x
            s2 += srow[r2][2] * yv;   // x_xy_y * y
            s3 += srow[r2][3] * yv;   // y_yy * y
            s4 += srow[r2][5] * xv;   // y_yx_x * x
        }
        g_SP[(0 * 1024 + blockIdx.x) * 64 + tid] = s1;
        g_SP[(1 * 1024 + blockIdx.x) * 64 + tid] = s2;
        g_SP[(2 * 1024 + blockIdx.x) * 64 + tid] = s3;
        g_SP[(3 * 1024 + blockIdx.x) * 64 + tid] = s4;
    }
}

// ---------------------------------------------------------------------------
// K3a: reduce 1024 s-vector partials to 16 (parallel over 16 CTAs)
// ---------------------------------------------------------------------------
__global__ void __launch_bounds__(256) k3a_reduce()
{
    int tid = threadIdx.x, v = tid >> 6, d = tid & 63, b = blockIdx.x;
    float s = 0.f;
    #pragma unroll 8
    for (int i = b * 64; i < b * 64 + 64; ++i)
        s += g_SP[((size_t)v * 1024 + i) * 64 + d];
    g_SP2[(v * 16 + b) * 64 + d] = s;
}

// ---------------------------------------------------------------------------
// K3b: final reduce + u1..u4 matvecs + edge branch
// ---------------------------------------------------------------------------
__global__ void __launch_bounds__(320) k3b_final(
    const float* __restrict__ uu_W1, const float* __restrict__ ui_W1,
    const float* __restrict__ ii_W1, const float* __restrict__ iu_W1,
    const float* __restrict__ edge_W, const float* __restrict__ edges_tab)
{
    __shared__ float sq[4][64];
    __shared__ float ev[64];
    int tid = threadIdx.x;
    if (tid < 256) {
        int v = tid >> 6, d = tid & 63;
        float tot = 0.f;
        #pragma unroll
        for (int b = 0; b < 16; ++b) tot += g_SP2[(v * 16 + b) * 64 + d];
        sq[v][d] = tot;
    } else {
        ev[tid - 256] = edges_tab[tid - 256] * 0.12f;
    }
    __syncthreads();
    if (tid < 256) {
        int v = tid >> 6, d = tid & 63;
        const float* W1 = (v == 0) ? uu_W1 : (v == 1) ? ui_W1 : (v == 2) ? ii_W1 : iu_W1;
        float u = 0.f;
        #pragma unroll
        for (int j = 0; j < 64; ++j) u += sq[v][j] * W1[j * 64 + d];
        g_U[v * 64 + d] = u;
    } else {
        int dd = tid - 256;
        float nv = 0.f;
        #pragma unroll
        for (int j = 0; j < 64; ++j) nv += ev[j] * edge_W[j * 64 + dd];
        nv = nv >= 0.f ? nv : 0.01f * nv;
        g_O3[dd] = 0.5f * (nv + ev[dd]);
    }
}

// ---------------------------------------------------------------------------
// K4: final elementwise assembly of the three outputs
// ---------------------------------------------------------------------------
__global__ void __launch_bounds__(256) k4_out(float* __restrict__ out)
{
    int idx = blockIdx.x * 256 + threadIdx.x;   // 0..262143
    int r = idx >> 6, d = idx & 63;
    float x_xx   = g_S[(size_t)r * 8 + 0];
    float x_xy_x = g_S[(size_t)r * 8 + 1];
    float y_yy   = g_S[(size_t)r * 8 + 3];
    float y_yx_y = g_S[(size_t)r * 8 + 4];
    float a1 = x_xx * g_U[d];         a1 = a1 >= 0.f ? a1 : 0.01f * a1;
    float a2 = x_xy_x * g_U[64 + d];  a2 = a2 >= 0.f ? a2 : 0.01f * a2;
    float b1 = y_yy * g_U[128 + d];   b1 = b1 >= 0.f ? b1 : 0.01f * b1;
    float b2 = y_yx_y * g_U[192 + d]; b2 = b2 >= 0.f ? b2 : 0.01f * b2;
    out[idx]          = ((a1 + a2) * 0.5f + g_X[idx]) * 0.5f;
    out[262144 + idx] = ((b1 + b2) * 0.5f + g_Y[idx]) * 0.5f;
    out[524288 + idx] = g_O3[d];
}

// ---------------------------------------------------------------------------
// launch
// ---------------------------------------------------------------------------
extern "C" void kernel_launch(void* const* d_in, const int* in_sizes, int n_in,
                              void* d_out, int out_size)
{
    const int*   user_emb   = (const int*)d_in[0];
    const int*   item_emb   = (const int*)d_in[1];
    const int*   edge_emb   = (const int*)d_in[2];
    const float* gender_tab = (const float*)d_in[3];
    const float* age_tab    = (const float*)d_in[4];
    const float* occ_tab    = (const float*)d_in[5];
    const float* area_tab   = (const float*)d_in[6];
    const float* user_W     = (const float*)d_in[7];
    const float* user_b     = (const float*)d_in[8];
    const float* rate_tab   = (const float*)d_in[9];
    const float* genre_W    = (const float*)d_in[10];
    const float* director_W = (const float*)d_in[11];
    const float* actor_W    = (const float*)d_in[12];
    const float* item_W     = (const float*)d_in[13];
    const float* item_b     = (const float*)d_in[14];
    const float* edges_tab  = (const float*)d_in[15];
    const float* uu_w       = (const float*)d_in[16];
    const float* ui_w       = (const float*)d_in[17];
    const float* iu_w       = (const float*)d_in[18];
    const float* ii_w       = (const float*)d_in[19];
    const float* edge_W     = (const float*)d_in[20];
    const float* uu_W1      = (const float*)d_in[21];
    const float* ui_W1      = (const float*)d_in[22];
    const float* iu_W1      = (const float*)d_in[23];
    const float* ii_W1      = (const float*)d_in[24];
    float* out = (float*)d_out;

    cudaFuncSetAttribute(k1_gemm, cudaFuncAttributeMaxDynamicSharedMemorySize, K1SMEM);

    k_dummy<<<1, 1>>>();
    k0_wt<<<164, 256>>>(genre_W, director_W, actor_W, item_W);
    k0_user<<<111, 256>>>(gender_tab, age_tab, occ_tab, area_tab, user_W, rate_tab, item_W);
    k1_gemm<<<dim3(32, 9), 256, K1SMEM>>>(item_emb);
    k2_finalize<<<1024, 256>>>(user_emb, item_emb, edge_emb, user_b, item_b, edges_tab,
                               uu_w, ui_w, iu_w, ii_w);
    k3a_reduce<<<16, 256>>>();
    k3b_final<<<1, 320>>>(uu_W1, ui_W1, ii_W1, iu_W1, edge_W, edges_tab);
    k4_out<<<1024, 256>>>(out);
}

// round 13
// speedup vs baseline: 1.5394x; 1.1336x over previous
#include <cuda_runtime.h>
#include <cuda_bf16.h>
#include <cstdint>

// ---------------------------------------------------------------------------
// Problem constants
// ---------------------------------------------------------------------------
#define BSZ    4096
#define ITEMW  10242
#define KT2    10496      // padded K: 128 (genre) + 2304 (director) + 8064 (actor)
#define NSLOT  10         // 0=genre, 1-2=director, 3-9=actor
#define PCX    64         // numerator columns per slot
#define BSTR   272        // B row stride bytes (128 bf16 + 16 pad)
#define BTILE  (64 * BSTR)    // 17408 B per B stage
#define K1SMEM (3 * BTILE)    // 52224 B (B ring only; A never staged)

// ---------------------------------------------------------------------------
// Device scratch (static globals; no allocations anywhere)
// ---------------------------------------------------------------------------
__device__ __align__(16) __nv_bfloat16 g_WT[64 * KT2];      // fused weights [d][k], shifts baked
__device__ float g_UF[3528 * 64];                            // user folds
__device__ float g_RF[6 * 64];                               // rate_tab @ item_W[0:64]
__device__ float g_part[(size_t)NSLOT * BSZ * PCX];          // GEMM partial numerators
__device__ float g_cnt[NSLOT * BSZ];                         // per-field bit counts
__device__ float g_X[BSZ * 64], g_Y[BSZ * 64];               // x, y vectors
__device__ float g_S[BSZ * 8];                               // per-row scalars (6 used)
__device__ float g_SP[4 * 1024 * 64];                        // per-CTA partials of s1..s4
__device__ float g_SP2[4 * 16 * 64];                         // stage-2 partials
__device__ float g_U[4 * 64];                                // u1..u4
__device__ float g_O3[64];                                   // edge-branch output row
__device__ int   g_ctr3;                                     // k3 last-CTA election (reset in-kernel)

// ---------------------------------------------------------------------------
// K0: fold all weight tables (merged k0_wt + k0_user).
//   blk < 164: item-side fold into g_WT (bf16), shifts baked:
//     genre   k [0,128):     bit kr = k - 1
//     director k [128,2432):  bit kr = k - 130
//     actor   k [2432,10496): bit kr = k - 2432
//   blk >= 164: user-side folds (32 rows per CTA) + rate fold.
// ---------------------------------------------------------------------------
__global__ void __launch_bounds__(256) k0_fold(
    const float* __restrict__ genre_W, const float* __restrict__ director_W,
    const float* __restrict__ actor_W, const float* __restrict__ item_W,
    const float* __restrict__ gender_tab, const float* __restrict__ age_tab,
    const float* __restrict__ occ_tab, const float* __restrict__ area_tab,
    const float* __restrict__ user_W, const float* __restrict__ rate_tab)
{
    __shared__ float sA[64][65];
    __shared__ float sB[64][65];
    int tid = threadIdx.x, d = tid & 63, q = tid >> 6;
    int blk = blockIdx.x;

    if (blk < 164) {
        // ------- item-side weight fold -------
        int kb = blk * 64;
        const float* W; int len, iwo, kr0;
        if (blk < 2)       { W = genre_W;    len = 25;   iwo = 64;  kr0 = 1;    }
        else if (blk < 38) { W = director_W; len = 2186; iwo = 128; kr0 = 130;  }
        else               { W = actor_W;    len = 8030; iwo = 192; kr0 = 2432; }

        #pragma unroll
        for (int j = q; j < 64; j += 4) sA[j][d] = item_W[(iwo + j) * 64 + d];
        #pragma unroll
        for (int kk = q; kk < 64; kk += 4) {
            int kr = kb + kk - kr0;
            sB[kk][d] = (kr >= 0 && kr < len) ? W[(size_t)kr * 64 + d] : 0.f;
        }
        __syncthreads();

        float res[16] = {};
        #pragma unroll 4
        for (int j = 0; j < 64; ++j) {
            float a = sA[j][d];
            #pragma unroll
            for (int i = 0; i < 16; ++i) res[i] += sB[q + 4 * i][j] * a;
        }
        __syncthreads();
        #pragma unroll
        for (int i = 0; i < 16; ++i) sB[q + 4 * i][d] = res[i];
        __syncthreads();

        for (int j = tid; j < 2048; j += 256) {
            int dd = j >> 5, w = j & 31;
            __nv_bfloat162 h = __floats2bfloat162_rn(sB[2 * w][dd], sB[2 * w + 1][dd]);
            *(uint32_t*)&g_WT[(size_t)dd * KT2 + kb + 2 * w] = *(uint32_t*)&h;
        }
    } else {
        // ------- user-side + rate fold -------
        int rb = (blk - 164) * 32;

        #pragma unroll
        for (int j = q; j < 64; j += 4) sA[j][d] = user_W[(192 + j) * 64 + d];

        for (int j2 = tid; j2 < 32 * 64; j2 += 256) {
            int rr = j2 >> 6, col = j2 & 63, r = rb + rr;
            float v = 0.f;
            if (r < 98)         v = gender_tab[r * 64 + col];
            else if (r < 105)   v = age_tab[(r - 98) * 64 + col];
            else if (r < 126)   v = occ_tab[(r - 105) * 64 + col];
            else if (r < 3528)  v = area_tab[(size_t)(r - 126) * 64 + col];
            else if (r < 3534)  v = rate_tab[(r - 3528) * 64 + col];
            sB[rr][col] = v;
        }
        __syncthreads();

        for (int rr = q; rr < 32; rr += 4) {
            int r = rb + rr;
            if (r >= 3534) continue;
            float v = 0.f;
            if (r >= 126 && r < 3528) {
                #pragma unroll 16
                for (int j = 0; j < 64; ++j) v += sB[rr][j] * sA[j][d];
            } else {
                const float* Wg = (r < 98) ? user_W : (r < 105) ? (user_W + 64 * 64)
                                : (r < 126) ? (user_W + 128 * 64) : item_W;
                #pragma unroll 16
                for (int j = 0; j < 64; ++j) v += sB[rr][j] * Wg[j * 64 + d];
            }
            if (r < 3528) g_UF[(size_t)r * 64 + d] = v;
            else          g_RF[(r - 3528) * 64 + d] = v;
        }
    }
}

// ---------------------------------------------------------------------------
// K1: HBM-bound bits GEMM (unchanged from R12 best).
//   M=128 tile, 8 warps each m16 x n64 -> A fragments warp-private, loaded
//   global->register directly in mma layout, quarter-step double-buffered.
//   B: bf16 WT tiles via cp.async 3-ring. Counts from prefetch regs.
// ---------------------------------------------------------------------------
__device__ __forceinline__ void cp16(uint32_t dst, const void* src) {
    asm volatile("cp.async.cg.shared.global [%0], [%1], 16;\n" :: "r"(dst), "l"(src));
}
__device__ __forceinline__ void ldsm4(uint32_t& r0, uint32_t& r1, uint32_t& r2, uint32_t& r3,
                                      uint32_t addr) {
    asm volatile("ldmatrix.sync.aligned.m8n8.x4.shared.b16 {%0,%1,%2,%3}, [%4];\n"
                 : "=r"(r0), "=r"(r1), "=r"(r2), "=r"(r3) : "r"(addr));
}
__device__ __forceinline__ uint32_t cvt2(int2 v) {
    return (v.x ? 0x3F80u : 0u) | (v.y ? 0x3F800000u : 0u);
}
__device__ __forceinline__ int stepbase(int s) {
    return (s == 0) ? 0 : (s < 19 ? 24 + (s - 1) * 128 : 2212 + (s - 19) * 128);
}

__device__ __forceinline__ void issueB(int s, int tid, uint32_t bbuf)
{
    const char* wt = (const char*)g_WT + (size_t)s * 256;
    #pragma unroll
    for (int it = 0; it < 4; ++it) {
        int j = it * 256 + tid;
        int dd = j >> 4, w16 = j & 15;
        cp16(bbuf + dd * BSTR + w16 * 16, wt + (size_t)dd * (KT2 * 2) + w16 * 16);
    }
    asm volatile("cp.async.commit_group;\n" ::: "memory");
}

__device__ __forceinline__ void loadA(const int* __restrict__ p0, const int* __restrict__ p1,
                                      int cq, bool guard, int2 (&B)[8])
{
    #pragma unroll
    for (int kl = 0; kl < 2; ++kl) {
        int c = cq + kl * 16;
        if (!guard) {
            B[kl * 4 + 0] = *(const int2*)(p0 + c);
            B[kl * 4 + 1] = *(const int2*)(p1 + c);
            B[kl * 4 + 2] = *(const int2*)(p0 + c + 8);
            B[kl * 4 + 3] = *(const int2*)(p1 + c + 8);
        } else {
            int2 z = make_int2(0, 0);
            B[kl * 4 + 0] = (c < ITEMW)     ? *(const int2*)(p0 + c)     : z;
            B[kl * 4 + 1] = (c < ITEMW)     ? *(const int2*)(p1 + c)     : z;
            B[kl * 4 + 2] = (c + 8 < ITEMW) ? *(const int2*)(p0 + c + 8) : z;
            B[kl * 4 + 3] = (c + 8 < ITEMW) ? *(const int2*)(p1 + c + 8) : z;
        }
    }
}

__device__ __forceinline__ void consume(const int2 (&Bf)[8], uint32_t bb, uint32_t boff0,
                                        int q, int cq, bool masked, int lo, int hi,
                                        float (&acc)[8][4], int& cnt0, int& cnt8)
{
    #pragma unroll
    for (int kl = 0; kl < 2; ++kl) {
        int2 x0 = Bf[kl * 4 + 0], x1 = Bf[kl * 4 + 1];
        int2 x2 = Bf[kl * 4 + 2], x3 = Bf[kl * 4 + 3];
        uint32_t a0 = cvt2(x0), a1 = cvt2(x1), a2 = cvt2(x2), a3 = cvt2(x3);
        if (masked) {
            int c = cq + kl * 16;
            int m0 = (c     >= lo) & (c     < hi);
            int m1 = (c + 1 >= lo) & (c + 1 < hi);
            int m8 = (c + 8 >= lo) & (c + 8 < hi);
            int m9 = (c + 9 >= lo) & (c + 9 < hi);
            cnt0 += (m0 ? x0.x : 0) + (m1 ? x0.y : 0) + (m8 ? x2.x : 0) + (m9 ? x2.y : 0);
            cnt8 += (m0 ? x1.x : 0) + (m1 ? x1.y : 0) + (m8 ? x3.x : 0) + (m9 ? x3.y : 0);
        } else {
            cnt0 += x0.x + x0.y + x2.x + x2.y;
            cnt8 += x1.x + x1.y + x3.x + x3.y;
        }
        uint32_t koff = (uint32_t)((q * 2 + kl) * 32);
        #pragma unroll
        for (int j = 0; j < 4; ++j) {
            uint32_t p0r, p1r, p2r, p3r;
            ldsm4(p0r, p1r, p2r, p3r, bb + boff0 + (uint32_t)(j * 16 * BSTR) + koff);
            #define HM(ACC, B0, B1)                                               \
                asm volatile(                                                     \
                    "mma.sync.aligned.m16n8k16.row.col.f32.bf16.bf16.f32 "        \
                    "{%0,%1,%2,%3}, {%4,%5,%6,%7}, {%8,%9}, {%0,%1,%2,%3};\n"     \
                    : "+f"(ACC[0]), "+f"(ACC[1]), "+f"(ACC[2]), "+f"(ACC[3])      \
                    : "r"(a0), "r"(a1), "r"(a2), "r"(a3), "r"(B0), "r"(B1))
            HM(acc[2 * j],     p0r, p1r);
            HM(acc[2 * j + 1], p2r, p3r);
            #undef HM
        }
    }
}

__device__ __forceinline__ void flushAC(float (&acc)[8][4], int& c0, int& c8, int slot,
                                        int rt, int lane, int w)
{
    int row = rt * 128 + w * 16 + (lane >> 2);
    int tg2 = 2 * (lane & 3);
    float* b0 = g_part + ((size_t)slot * BSZ + row) * PCX;
    float* b8 = b0 + 8 * PCX;
    #pragma unroll
    for (int t = 0; t < 8; ++t) {
        int col = t * 8 + tg2;
        *(float2*)&b0[col] = make_float2(acc[t][0], acc[t][1]);
        *(float2*)&b8[col] = make_float2(acc[t][2], acc[t][3]);
        acc[t][0] = acc[t][1] = acc[t][2] = acc[t][3] = 0.f;
    }
    int s1 = c0, s2 = c8;
    s1 += __shfl_xor_sync(0xffffffffu, s1, 1);
    s1 += __shfl_xor_sync(0xffffffffu, s1, 2);
    s2 += __shfl_xor_sync(0xffffffffu, s2, 1);
    s2 += __shfl_xor_sync(0xffffffffu, s2, 2);
    if ((lane & 3) == 0) {
        g_cnt[slot * BSZ + row]     = (float)s1;
        g_cnt[slot * BSZ + row + 8] = (float)s2;
    }
    c0 = 0; c8 = 0;
}

__global__ void __launch_bounds__(256, 2) k1_gemm(const int* __restrict__ item)
{
    extern __shared__ __align__(16) uint8_t smem[];
    uint32_t sB = (uint32_t)__cvta_generic_to_shared(smem);

    int tid = threadIdx.x, lane = tid & 31, w = tid >> 5;
    int rt = blockIdx.x, sp = blockIdx.y;
    int s0, s1;
    if (sp == 0)      { s0 = 0;  s1 = 10; }
    else if (sp == 1) { s0 = 10; s1 = 19; }
    else              { s0 = 19 + 9 * (sp - 2); s1 = s0 + 9; }

    int qj2 = 2 * (lane & 3);
    long row0 = (long)(rt * 128 + w * 16 + (lane >> 2));
    const int* p0 = item + row0 * ITEMW;
    const int* p1 = p0 + (long)8 * ITEMW;
    int tsel = (lane >> 4) & 1;
    int col8 = ((lane >> 3) & 1) * 16;
    uint32_t boff0 = (uint32_t)((tsel * 8 + (lane & 7)) * BSTR + col8);

    float acc[8][4] = {};
    int cnt0 = 0, cnt8 = 0;
    int2 buf[2][8];

    issueB(s0,     tid, sB + (s0 % 3) * BTILE);
    issueB(s0 + 1, tid, sB + ((s0 + 1) % 3) * BTILE);
    loadA(p0, p1, stepbase(s0) + qj2, false, buf[0]);   // s0 is never 81

    for (int s = s0; s < s1; ++s) {
        if (s + 1 < s1) { asm volatile("cp.async.wait_group 1;\n" ::: "memory"); }
        else            { asm volatile("cp.async.wait_group 0;\n" ::: "memory"); }
        __syncthreads();
        if (s + 2 < s1) issueB(s + 2, tid, sB + ((s + 2) % 3) * BTILE);

        int base = stepbase(s);
        bool masked = (s <= 1) || (s == 18);
        int lo = (s == 0) ? 1 : 26;
        int hi = (s == 0) ? 26 : 2212;
        uint32_t bb = sB + (s % 3) * BTILE;

        #pragma unroll
        for (int q = 0; q < 4; ++q) {
            int ns = s, nq = q + 1;
            if (nq == 4) { nq = 0; ns = s + 1; }
            if (ns < s1)
                loadA(p0, p1, stepbase(ns) + nq * 32 + qj2, ns == 81, buf[(q + 1) & 1]);
            consume(buf[q & 1], bb, boff0, q, base + q * 32 + qj2,
                    masked, lo, hi, acc, cnt0, cnt8);
        }
        if (sp == 0 && s == 0) flushAC(acc, cnt0, cnt8, 0, rt, lane, w);   // genre
    }
    flushAC(acc, cnt0, cnt8, (sp == 0) ? 1 : sp + 1, rt, lane, w);
}

// ---------------------------------------------------------------------------
// K2: reduce partial slots, finalize x / y / edge, per-row scalars,
// s-vector partials. 4 rows per CTA, 1024 CTAs. (unchanged)
// ---------------------------------------------------------------------------
__global__ void __launch_bounds__(256) k2_finalize(
    const int* __restrict__ user_emb, const int* __restrict__ item,
    const int* __restrict__ edge_emb,
    const float* __restrict__ user_b, const float* __restrict__ item_b,
    const float* __restrict__ edges_tab,
    const float* __restrict__ uu_w, const float* __restrict__ ui_w,
    const float* __restrict__ iu_w, const float* __restrict__ ii_w)
{
    int tid = threadIdx.x, lane = tid & 31, warp = tid >> 5;
    int rr = tid >> 6, d = tid & 63;
    int row = blockIdx.x * 4 + rr;

    float ng = g_part[((size_t)0 * BSZ + row) * PCX + d];
    float nd = g_part[((size_t)1 * BSZ + row) * PCX + d]
             + g_part[((size_t)2 * BSZ + row) * PCX + d];
    float na = 0.f, ca = 0.f;
    #pragma unroll
    for (int t = 3; t < NSLOT; ++t) {
        na += g_part[((size_t)t * BSZ + row) * PCX + d];
        ca += g_cnt[t * BSZ + row];
    }
    float cg = g_cnt[0 * BSZ + row];
    float cd = g_cnt[1 * BSZ + row] + g_cnt[2 * BSZ + row];

    int ri = item[(long)row * ITEMW];
    float y = (g_RF[ri * 64 + d] + ng / cg + nd / cd + na / ca + item_b[d]) * 0.12f;

    int gi = user_emb[row * 4 + 0], ai = user_emb[row * 4 + 1];
    int oi = user_emb[row * 4 + 2], ari = user_emb[row * 4 + 3];
    float x = (g_UF[gi * 64 + d] + g_UF[(98 + ai) * 64 + d] + g_UF[(105 + oi) * 64 + d]
             + g_UF[(size_t)(126 + ari) * 64 + d] + user_b[d]) * 0.12f;
    float e = edges_tab[edge_emb[row] * 64 + d] * 0.12f;

    g_X[row * 64 + d] = x;
    g_Y[row * 64 + d] = y;

    __shared__ float sx[4][64], sy[4][64];
    __shared__ float red[8][6], srow[4][6];
    sx[rr][d] = x; sy[rr][d] = y;

    float xe = x * e, ye = y * e;
    float pr[6] = { xe * uu_w[d], xe * ui_w[d], ye * ui_w[d],
                    ye * ii_w[d], ye * iu_w[d], xe * iu_w[d] };
    #pragma unroll
    for (int o = 16; o; o >>= 1) {
        #pragma unroll
        for (int j = 0; j < 6; ++j) pr[j] += __shfl_xor_sync(0xffffffffu, pr[j], o);
    }
    if (lane == 0) {
        #pragma unroll
        for (int j = 0; j < 6; ++j) red[warp][j] = pr[j];
    }
    __syncthreads();
    if (tid < 24) {
        int r2 = tid / 6, j = tid % 6;
        float v = red[2 * r2][j] + red[2 * r2 + 1][j];
        srow[r2][j] = v;
        g_S[(size_t)(blockIdx.x * 4 + r2) * 8 + j] = v;
    }
    __syncthreads();
    if (tid < 64) {
        float s1 = 0, s2 = 0, s3 = 0, s4 = 0;
        #pragma unroll
        for (int r2 = 0; r2 < 4; ++r2) {
            float xv = sx[r2][tid], yv = sy[r2][tid];
            s1 += srow[r2][0] * xv;   // x_xx * x
            s2 += srow[r2][2] * yv;   // x_xy_y * y
            s3 += srow[r2][3] * yv;   // y_yy * y
            s4 += srow[r2][5] * xv;   // y_yx_x * x
        }
        g_SP[(0 * 1024 + blockIdx.x) * 64 + tid] = s1;
        g_SP[(1 * 1024 + blockIdx.x) * 64 + tid] = s2;
        g_SP[(2 * 1024 + blockIdx.x) * 64 + tid] = s3;
        g_SP[(3 * 1024 + blockIdx.x) * 64 + tid] = s4;
    }
}

// ---------------------------------------------------------------------------
// K3: reduce 1024 s-vector partials to 16 across 16 CTAs; the LAST CTA
// (deterministic atomic election, counter reset in-kernel) finishes the
// reduction, computes u1..u4 matvecs and the edge branch.
// ---------------------------------------------------------------------------
__global__ void __launch_bounds__(256) k3_reduce(
    const float* __restrict__ uu_W1, const float* __restrict__ ui_W1,
    const float* __restrict__ ii_W1, const float* __restrict__ iu_W1,
    const float* __restrict__ edge_W, const float* __restrict__ edges_tab)
{
    int tid = threadIdx.x, v = tid >> 6, d = tid & 63, b = blockIdx.x;
    float s = 0.f;
    #pragma unroll 8
    for (int i = b * 64; i < b * 64 + 64; ++i)
        s += g_SP[((size_t)v * 1024 + i) * 64 + d];
    g_SP2[(v * 16 + b) * 64 + d] = s;

    __threadfence();
    __shared__ int amlast;
    if (tid == 0) amlast = (atomicAdd(&g_ctr3, 1) == 15) ? 1 : 0;
    __syncthreads();
    if (!amlast) return;

    // ---- finale (only the last CTA) ----
    __shared__ float sq[4][64];
    __shared__ float ev[64];
    float tot = 0.f;
    #pragma unroll
    for (int bb = 0; bb < 16; ++bb) tot += g_SP2[(v * 16 + bb) * 64 + d];
    sq[v][d] = tot;
    if (tid < 64) ev[tid] = edges_tab[tid] * 0.12f;
    __syncthreads();

    const float* W1 = (v == 0) ? uu_W1 : (v == 1) ? ui_W1 : (v == 2) ? ii_W1 : iu_W1;
    float u = 0.f;
    #pragma unroll
    for (int j = 0; j < 64; ++j) u += sq[v][j] * W1[j * 64 + d];
    g_U[v * 64 + d] = u;

    if (tid < 64) {
        float nv = 0.f;
        #pragma unroll
        for (int j = 0; j < 64; ++j) nv += ev[j] * edge_W[j * 64 + tid];
        nv = nv >= 0.f ? nv : 0.01f * nv;
        g_O3[tid] = 0.5f * (nv + ev[tid]);
    }
    if (tid == 0) g_ctr3 = 0;   // reset for next graph replay (deterministic)
}

// ---------------------------------------------------------------------------
// K4: final elementwise assembly of the three outputs
// ---------------------------------------------------------------------------
__global__ void __launch_bounds__(256) k4_out(float* __restrict__ out)
{
    int idx = blockIdx.x * 256 + threadIdx.x;   // 0..262143
    int r = idx >> 6, d = idx & 63;
    float x_xx   = g_S[(size_t)r * 8 + 0];
    float x_xy_x = g_S[(size_t)r * 8 + 1];
    float y_yy   = g_S[(size_t)r * 8 + 3];
    float y_yx_y = g_S[(size_t)r * 8 + 4];
    float a1 = x_xx * g_U[d];         a1 = a1 >= 0.f ? a1 : 0.01f * a1;
    float a2 = x_xy_x * g_U[64 + d];  a2 = a2 >= 0.f ? a2 : 0.01f * a2;
    float b1 = y_yy * g_U[128 + d];   b1 = b1 >= 0.f ? b1 : 0.01f * b1;
    float b2 = y_yx_y * g_U[192 + d]; b2 = b2 >= 0.f ? b2 : 0.01f * b2;
    out[idx]          = ((a1 + a2) * 0.5f + g_X[idx]) * 0.5f;
    out[262144 + idx] = ((b1 + b2) * 0.5f + g_Y[idx]) * 0.5f;
    out[524288 + idx] = g_O3[d];
}

// ---------------------------------------------------------------------------
// launch (5 kernels)
// ---------------------------------------------------------------------------
extern "C" void kernel_launch(void* const* d_in, const int* in_sizes, int n_in,
                              void* d_out, int out_size)
{
    const int*   user_emb   = (const int*)d_in[0];
    const int*   item_emb   = (const int*)d_in[1];
    const int*   edge_emb   = (const int*)d_in[2];
    const float* gender_tab = (const float*)d_in[3];
    const float* age_tab    = (const float*)d_in[4];
    const float* occ_tab    = (const float*)d_in[5];
    const float* area_tab   = (const float*)d_in[6];
    const float* user_W     = (const float*)d_in[7];
    const float* user_b     = (const float*)d_in[8];
    const float* rate_tab   = (const float*)d_in[9];
    const float* genre_W    = (const float*)d_in[10];
    const float* director_W = (const float*)d_in[11];
    const float* actor_W    = (const float*)d_in[12];
    const float* item_W     = (const float*)d_in[13];
    const float* item_b     = (const float*)d_in[14];
    const float* edges_tab  = (const float*)d_in[15];
    const float* uu_w       = (const float*)d_in[16];
    const float* ui_w       = (const float*)d_in[17];
    const float* iu_w       = (const float*)d_in[18];
    const float* ii_w       = (const float*)d_in[19];
    const float* edge_W     = (const float*)d_in[20];
    const float* uu_W1      = (const float*)d_in[21];
    const float* ui_W1      = (const float*)d_in[22];
    const float* iu_W1      = (const float*)d_in[23];
    const float* ii_W1      = (const float*)d_in[24];
    float* out = (float*)d_out;

    cudaFuncSetAttribute(k1_gemm, cudaFuncAttributeMaxDynamicSharedMemorySize, K1SMEM);

    k0_fold<<<275, 256>>>(genre_W, director_W, actor_W, item_W,
                          gender_tab, age_tab, occ_tab, area_tab, user_W, rate_tab);
    k1_gemm<<<dim3(32, 9), 256, K1SMEM>>>(item_emb);
    k2_finalize<<<1024, 256>>>(user_emb, item_emb, edge_emb, user_b, item_b, edges_tab,
                               uu_w, ui_w, iu_w, ii_w);
    k3_reduce<<<16, 256>>>(uu_W1, ui_W1, ii_W1, iu_W1, edge_W, edges_tab);
    k4_out<<<1024, 256>>>(out);
}

// round 14
// speedup vs baseline: 1.5400x; 1.0004x over previous
#include <cuda_runtime.h>
#include <cuda_bf16.h>
#include <cstdint>

// ---------------------------------------------------------------------------
// Problem constants
// ---------------------------------------------------------------------------
#define BSZ    4096
#define ITEMW  10242
#define KT2    10496      // padded K: 128 (genre) + 2304 (director) + 8064 (actor)
#define NSLOT  10         // 0=genre, 1-2=director, 3-9=actor
#define PCX    64         // numerator columns per slot
#define BSTR   272        // B row stride bytes (128 bf16 + 16 pad)
#define BTILE  (64 * BSTR)    // 17408 B per B stage
#define K1SMEM (3 * BTILE)    // 52224 B (B ring only; A never staged)

// ---------------------------------------------------------------------------
// Device scratch (static globals; no allocations anywhere)
// ---------------------------------------------------------------------------
__device__ __align__(16) __nv_bfloat16 g_WT[64 * KT2];      // fused weights [d][k], shifts baked
__device__ float g_UF[3528 * 64];                            // user folds
__device__ float g_RF[6 * 64];                               // rate_tab @ item_W[0:64]
__device__ float g_part[(size_t)NSLOT * BSZ * PCX];          // GEMM partial numerators
__device__ float g_cnt[NSLOT * BSZ];                         // per-field bit counts
__device__ float g_X[BSZ * 64], g_Y[BSZ * 64];               // x, y vectors
__device__ float g_S[BSZ * 8];                               // per-row scalars (6 used)
__device__ float g_SP[4 * 1024 * 64];                        // per-CTA partials of s1..s4
__device__ float g_SP2[4 * 16 * 64];                         // stage-2 partials
__device__ float g_U[4 * 64];                                // u1..u4
__device__ float g_O3[64];                                   // edge-branch output row
__device__ int   g_ctr3;                                     // k3 last-CTA election (reset in-kernel)

// ---------------------------------------------------------------------------
// K0: fold all weight tables (merged k0_wt + k0_user).
//   blk < 164: item-side fold into g_WT (bf16), shifts baked:
//     genre   k [0,128):     bit kr = k - 1
//     director k [128,2432):  bit kr = k - 130
//     actor   k [2432,10496): bit kr = k - 2432
//   blk >= 164: user-side folds (32 rows per CTA) + rate fold.
// ---------------------------------------------------------------------------
__global__ void __launch_bounds__(256) k0_fold(
    const float* __restrict__ genre_W, const float* __restrict__ director_W,
    const float* __restrict__ actor_W, const float* __restrict__ item_W,
    const float* __restrict__ gender_tab, const float* __restrict__ age_tab,
    const float* __restrict__ occ_tab, const float* __restrict__ area_tab,
    const float* __restrict__ user_W, const float* __restrict__ rate_tab)
{
    __shared__ float sA[64][65];
    __shared__ float sB[64][65];
    int tid = threadIdx.x, d = tid & 63, q = tid >> 6;
    int blk = blockIdx.x;

    if (blk < 164) {
        // ------- item-side weight fold -------
        int kb = blk * 64;
        const float* W; int len, iwo, kr0;
        if (blk < 2)       { W = genre_W;    len = 25;   iwo = 64;  kr0 = 1;    }
        else if (blk < 38) { W = director_W; len = 2186; iwo = 128; kr0 = 130;  }
        else               { W = actor_W;    len = 8030; iwo = 192; kr0 = 2432; }

        #pragma unroll
        for (int j = q; j < 64; j += 4) sA[j][d] = item_W[(iwo + j) * 64 + d];
        #pragma unroll
        for (int kk = q; kk < 64; kk += 4) {
            int kr = kb + kk - kr0;
            sB[kk][d] = (kr >= 0 && kr < len) ? W[(size_t)kr * 64 + d] : 0.f;
        }
        __syncthreads();

        float res[16] = {};
        #pragma unroll 4
        for (int j = 0; j < 64; ++j) {
            float a = sA[j][d];
            #pragma unroll
            for (int i = 0; i < 16; ++i) res[i] += sB[q + 4 * i][j] * a;
        }
        __syncthreads();
        #pragma unroll
        for (int i = 0; i < 16; ++i) sB[q + 4 * i][d] = res[i];
        __syncthreads();

        for (int j = tid; j < 2048; j += 256) {
            int dd = j >> 5, w = j & 31;
            __nv_bfloat162 h = __floats2bfloat162_rn(sB[2 * w][dd], sB[2 * w + 1][dd]);
            *(uint32_t*)&g_WT[(size_t)dd * KT2 + kb + 2 * w] = *(uint32_t*)&h;
        }
    } else {
        // ------- user-side + rate fold -------
        int rb = (blk - 164) * 32;

        #pragma unroll
        for (int j = q; j < 64; j += 4) sA[j][d] = user_W[(192 + j) * 64 + d];

        for (int j2 = tid; j2 < 32 * 64; j2 += 256) {
            int rr = j2 >> 6, col = j2 & 63, r = rb + rr;
            float v = 0.f;
            if (r < 98)         v = gender_tab[r * 64 + col];
            else if (r < 105)   v = age_tab[(r - 98) * 64 + col];
            else if (r < 126)   v = occ_tab[(r - 105) * 64 + col];
            else if (r < 3528)  v = area_tab[(size_t)(r - 126) * 64 + col];
            else if (r < 3534)  v = rate_tab[(r - 3528) * 64 + col];
            sB[rr][col] = v;
        }
        __syncthreads();

        for (int rr = q; rr < 32; rr += 4) {
            int r = rb + rr;
            if (r >= 3534) continue;
            float v = 0.f;
            if (r >= 126 && r < 3528) {
                #pragma unroll 16
                for (int j = 0; j < 64; ++j) v += sB[rr][j] * sA[j][d];
            } else {
                const float* Wg = (r < 98) ? user_W : (r < 105) ? (user_W + 64 * 64)
                                : (r < 126) ? (user_W + 128 * 64) : item_W;
                #pragma unroll 16
                for (int j = 0; j < 64; ++j) v += sB[rr][j] * Wg[j * 64 + d];
            }
            if (r < 3528) g_UF[(size_t)r * 64 + d] = v;
            else          g_RF[(r - 3528) * 64 + d] = v;
        }
    }
}

// ---------------------------------------------------------------------------
// K1: HBM-bound bits GEMM (unchanged from R12 best).
//   M=128 tile, 8 warps each m16 x n64 -> A fragments warp-private, loaded
//   global->register directly in mma layout, quarter-step double-buffered.
//   B: bf16 WT tiles via cp.async 3-ring. Counts from prefetch regs.
// ---------------------------------------------------------------------------
__device__ __forceinline__ void cp16(uint32_t dst, const void* src) {
    asm volatile("cp.async.cg.shared.global [%0], [%1], 16;\n" :: "r"(dst), "l"(src));
}
__device__ __forceinline__ void ldsm4(uint32_t& r0, uint32_t& r1, uint32_t& r2, uint32_t& r3,
                                      uint32_t addr) {
    asm volatile("ldmatrix.sync.aligned.m8n8.x4.shared.b16 {%0,%1,%2,%3}, [%4];\n"
                 : "=r"(r0), "=r"(r1), "=r"(r2), "=r"(r3) : "r"(addr));
}
__device__ __forceinline__ uint32_t cvt2(int2 v) {
    return (v.x ? 0x3F80u : 0u) | (v.y ? 0x3F800000u : 0u);
}
__device__ __forceinline__ int stepbase(int s) {
    return (s == 0) ? 0 : (s < 19 ? 24 + (s - 1) * 128 : 2212 + (s - 19) * 128);
}

__device__ __forceinline__ void issueB(int s, int tid, uint32_t bbuf)
{
    const char* wt = (const char*)g_WT + (size_t)s * 256;
    #pragma unroll
    for (int it = 0; it < 4; ++it) {
        int j = it * 256 + tid;
        int dd = j >> 4, w16 = j & 15;
        cp16(bbuf + dd * BSTR + w16 * 16, wt + (size_t)dd * (KT2 * 2) + w16 * 16);
    }
    asm volatile("cp.async.commit_group;\n" ::: "memory");
}

__device__ __forceinline__ void loadA(const int* __restrict__ p0, const int* __restrict__ p1,
                                      int cq, bool guard, int2 (&B)[8])
{
    #pragma unroll
    for (int kl = 0; kl < 2; ++kl) {
        int c = cq + kl * 16;
        if (!guard) {
            B[kl * 4 + 0] = *(const int2*)(p0 + c);
            B[kl * 4 + 1] = *(const int2*)(p1 + c);
            B[kl * 4 + 2] = *(const int2*)(p0 + c + 8);
            B[kl * 4 + 3] = *(const int2*)(p1 + c + 8);
        } else {
            int2 z = make_int2(0, 0);
            B[kl * 4 + 0] = (c < ITEMW)     ? *(const int2*)(p0 + c)     : z;
            B[kl * 4 + 1] = (c < ITEMW)     ? *(const int2*)(p1 + c)     : z;
            B[kl * 4 + 2] = (c + 8 < ITEMW) ? *(const int2*)(p0 + c + 8) : z;
            B[kl * 4 + 3] = (c + 8 < ITEMW) ? *(const int2*)(p1 + c + 8) : z;
        }
    }
}

__device__ __forceinline__ void consume(const int2 (&Bf)[8], uint32_t bb, uint32_t boff0,
                                        int q, int cq, bool masked, int lo, int hi,
                                        float (&acc)[8][4], int& cnt0, int& cnt8)
{
    #pragma unroll
    for (int kl = 0; kl < 2; ++kl) {
        int2 x0 = Bf[kl * 4 + 0], x1 = Bf[kl * 4 + 1];
        int2 x2 = Bf[kl * 4 + 2], x3 = Bf[kl * 4 + 3];
        uint32_t a0 = cvt2(x0), a1 = cvt2(x1), a2 = cvt2(x2), a3 = cvt2(x3);
        if (masked) {
            int c = cq + kl * 16;
            int m0 = (c     >= lo) & (c     < hi);
            int m1 = (c + 1 >= lo) & (c + 1 < hi);
            int m8 = (c + 8 >= lo) & (c + 8 < hi);
            int m9 = (c + 9 >= lo) & (c + 9 < hi);
            cnt0 += (m0 ? x0.x : 0) + (m1 ? x0.y : 0) + (m8 ? x2.x : 0) + (m9 ? x2.y : 0);
            cnt8 += (m0 ? x1.x : 0) + (m1 ? x1.y : 0) + (m8 ? x3.x : 0) + (m9 ? x3.y : 0);
        } else {
            cnt0 += x0.x + x0.y + x2.x + x2.y;
            cnt8 += x1.x + x1.y + x3.x + x3.y;
        }
        uint32_t koff = (uint32_t)((q * 2 + kl) * 32);
        #pragma unroll
        for (int j = 0; j < 4; ++j) {
            uint32_t p0r, p1r, p2r, p3r;
            ldsm4(p0r, p1r, p2r, p3r, bb + boff0 + (uint32_t)(j * 16 * BSTR) + koff);
            #define HM(ACC, B0, B1)                                               \
                asm volatile(                                                     \
                    "mma.sync.aligned.m16n8k16.row.col.f32.bf16.bf16.f32 "        \
                    "{%0,%1,%2,%3}, {%4,%5,%6,%7}, {%8,%9}, {%0,%1,%2,%3};\n"     \
                    : "+f"(ACC[0]), "+f"(ACC[1]), "+f"(ACC[2]), "+f"(ACC[3])      \
                    : "r"(a0), "r"(a1), "r"(a2), "r"(a3), "r"(B0), "r"(B1))
            HM(acc[2 * j],     p0r, p1r);
            HM(acc[2 * j + 1], p2r, p3r);
            #undef HM
        }
    }
}

__device__ __forceinline__ void flushAC(float (&acc)[8][4], int& c0, int& c8, int slot,
                                        int rt, int lane, int w)
{
    int row = rt * 128 + w * 16 + (lane >> 2);
    int tg2 = 2 * (lane & 3);
    float* b0 = g_part + ((size_t)slot * BSZ + row) * PCX;
    float* b8 = b0 + 8 * PCX;
    #pragma unroll
    for (int t = 0; t < 8; ++t) {
        int col = t * 8 + tg2;
        *(float2*)&b0[col] = make_float2(acc[t][0], acc[t][1]);
        *(float2*)&b8[col] = make_float2(acc[t][2], acc[t][3]);
        acc[t][0] = acc[t][1] = acc[t][2] = acc[t][3] = 0.f;
    }
    int s1 = c0, s2 = c8;
    s1 += __shfl_xor_sync(0xffffffffu, s1, 1);
    s1 += __shfl_xor_sync(0xffffffffu, s1, 2);
    s2 += __shfl_xor_sync(0xffffffffu, s2, 1);
    s2 += __shfl_xor_sync(0xffffffffu, s2, 2);
    if ((lane & 3) == 0) {
        g_cnt[slot * BSZ + row]     = (float)s1;
        g_cnt[slot * BSZ + row + 8] = (float)s2;
    }
    c0 = 0; c8 = 0;
}

__global__ void __launch_bounds__(256, 2) k1_gemm(const int* __restrict__ item)
{
    extern __shared__ __align__(16) uint8_t smem[];
    uint32_t sB = (uint32_t)__cvta_generic_to_shared(smem);

    int tid = threadIdx.x, lane = tid & 31, w = tid >> 5;
    int rt = blockIdx.x, sp = blockIdx.y;
    int s0, s1;
    if (sp == 0)      { s0 = 0;  s1 = 10; }
    else if (sp == 1) { s0 = 10; s1 = 19; }
    else              { s0 = 19 + 9 * (sp - 2); s1 = s0 + 9; }

    int qj2 = 2 * (lane & 3);
    long row0 = (long)(rt * 128 + w * 16 + (lane >> 2));
    const int* p0 = item + row0 * ITEMW;
    const int* p1 = p0 + (long)8 * ITEMW;
    int tsel = (lane >> 4) & 1;
    int col8 = ((lane >> 3) & 1) * 16;
    uint32_t boff0 = (uint32_t)((tsel * 8 + (lane & 7)) * BSTR + col8);

    float acc[8][4] = {};
    int cnt0 = 0, cnt8 = 0;
    int2 buf[2][8];

    issueB(s0,     tid, sB + (s0 % 3) * BTILE);
    issueB(s0 + 1, tid, sB + ((s0 + 1) % 3) * BTILE);
    loadA(p0, p1, stepbase(s0) + qj2, false, buf[0]);   // s0 is never 81

    for (int s = s0; s < s1; ++s) {
        if (s + 1 < s1) { asm volatile("cp.async.wait_group 1;\n" ::: "memory"); }
        else            { asm volatile("cp.async.wait_group 0;\n" ::: "memory"); }
        __syncthreads();
        if (s + 2 < s1) issueB(s + 2, tid, sB + ((s + 2) % 3) * BTILE);

        int base = stepbase(s);
        bool masked = (s <= 1) || (s == 18);
        int lo = (s == 0) ? 1 : 26;
        int hi = (s == 0) ? 26 : 2212;
        uint32_t bb = sB + (s % 3) * BTILE;

        #pragma unroll
        for (int q = 0; q < 4; ++q) {
            int ns = s, nq = q + 1;
            if (nq == 4) { nq = 0; ns = s + 1; }
            if (ns < s1)
                loadA(p0, p1, stepbase(ns) + nq * 32 + qj2, ns == 81, buf[(q + 1) & 1]);
            consume(buf[q & 1], bb, boff0, q, base + q * 32 + qj2,
                    masked, lo, hi, acc, cnt0, cnt8);
        }
        if (sp == 0 && s == 0) flushAC(acc, cnt0, cnt8, 0, rt, lane, w);   // genre
    }
    flushAC(acc, cnt0, cnt8, (sp == 0) ? 1 : sp + 1, rt, lane, w);
}

// ---------------------------------------------------------------------------
// K2: reduce partial slots, finalize x / y / edge, per-row scalars,
// s-vector partials. 4 rows per CTA, 1024 CTAs. (unchanged)
// ---------------------------------------------------------------------------
__global__ void __launch_bounds__(256) k2_finalize(
    const int* __restrict__ user_emb, const int* __restrict__ item,
    const int* __restrict__ edge_emb,
    const float* __restrict__ user_b, const float* __restrict__ item_b,
    const float* __restrict__ edges_tab,
    const float* __restrict__ uu_w, const float* __restrict__ ui_w,
    const float* __restrict__ iu_w, const float* __restrict__ ii_w)
{
    int tid = threadIdx.x, lane = tid & 31, warp = tid >> 5;
    int rr = tid >> 6, d = tid & 63;
    int row = blockIdx.x * 4 + rr;

    float ng = g_part[((size_t)0 * BSZ + row) * PCX + d];
    float nd = g_part[((size_t)1 * BSZ + row) * PCX + d]
             + g_part[((size_t)2 * BSZ + row) * PCX + d];
    float na = 0.f, ca = 0.f;
    #pragma unroll
    for (int t = 3; t < NSLOT; ++t) {
        na += g_part[((size_t)t * BSZ + row) * PCX + d];
        ca += g_cnt[t * BSZ + row];
    }
    float cg = g_cnt[0 * BSZ + row];
    float cd = g_cnt[1 * BSZ + row] + g_cnt[2 * BSZ + row];

    int ri = item[(long)row * ITEMW];
    float y = (g_RF[ri * 64 + d] + ng / cg + nd / cd + na / ca + item_b[d]) * 0.12f;

    int gi = user_emb[row * 4 + 0], ai = user_emb[row * 4 + 1];
    int oi = user_emb[row * 4 + 2], ari = user_emb[row * 4 + 3];
    float x = (g_UF[gi * 64 + d] + g_UF[(98 + ai) * 64 + d] + g_UF[(105 + oi) * 64 + d]
             + g_UF[(size_t)(126 + ari) * 64 + d] + user_b[d]) * 0.12f;
    float e = edges_tab[edge_emb[row] * 64 + d] * 0.12f;

    g_X[row * 64 + d] = x;
    g_Y[row * 64 + d] = y;

    __shared__ float sx[4][64], sy[4][64];
    __shared__ float red[8][6], srow[4][6];
    sx[rr][d] = x; sy[rr][d] = y;

    float xe = x * e, ye = y * e;
    float pr[6] = { xe * uu_w[d], xe * ui_w[d], ye * ui_w[d],
                    ye * ii_w[d], ye * iu_w[d], xe * iu_w[d] };
    #pragma unroll
    for (int o = 16; o; o >>= 1) {
        #pragma unroll
        for (int j = 0; j < 6; ++j) pr[j] += __shfl_xor_sync(0xffffffffu, pr[j], o);
    }
    if (lane == 0) {
        #pragma unroll
        for (int j = 0; j < 6; ++j) red[warp][j] = pr[j];
    }
    __syncthreads();
    if (tid < 24) {
        int r2 = tid / 6, j = tid % 6;
        float v = red[2 * r2][j] + red[2 * r2 + 1][j];
        srow[r2][j] = v;
        g_S[(size_t)(blockIdx.x * 4 + r2) * 8 + j] = v;
    }
    __syncthreads();
    if (tid < 64) {
        float s1 = 0, s2 = 0, s3 = 0, s4 = 0;
        #pragma unroll
        for (int r2 = 0; r2 < 4; ++r2) {
            float xv = sx[r2][tid], yv = sy[r2][tid];
            s1 += srow[r2][0] * xv;   // x_xx * x
            s2 += srow[r2][2] * yv;   // x_xy_y * y
            s3 += srow[r2][3] * yv;   // y_yy * y
            s4 += srow[r2][5] * xv;   // y_yx_x * x
        }
        g_SP[(0 * 1024 + blockIdx.x) * 64 + tid] = s1;
        g_SP[(1 * 1024 + blockIdx.x) * 64 + tid] = s2;
        g_SP[(2 * 1024 + blockIdx.x) * 64 + tid] = s3;
        g_SP[(3 * 1024 + blockIdx.x) * 64 + tid] = s4;
    }
}

// ---------------------------------------------------------------------------
// K3: reduce 1024 s-vector partials to 16 across 16 CTAs; the LAST CTA
// (deterministic atomic election, counter reset in-kernel) finishes the
// reduction, computes u1..u4 matvecs and the edge branch.
// ---------------------------------------------------------------------------
__global__ void __launch_bounds__(256) k3_reduce(
    const float* __restrict__ uu_W1, const float* __restrict__ ui_W1,
    const float* __restrict__ ii_W1, const float* __restrict__ iu_W1,
    const float* __restrict__ edge_W, const float* __restrict__ edges_tab)
{
    int tid = threadIdx.x, v = tid >> 6, d = tid & 63, b = blockIdx.x;
    float s = 0.f;
    #pragma unroll 8
    for (int i = b * 64; i < b * 64 + 64; ++i)
        s += g_SP[((size_t)v * 1024 + i) * 64 + d];
    g_SP2[(v * 16 + b) * 64 + d] = s;

    __threadfence();
    __shared__ int amlast;
    if (tid == 0) amlast = (atomicAdd(&g_ctr3, 1) == 15) ? 1 : 0;
    __syncthreads();
    if (!amlast) return;

    // ---- finale (only the last CTA) ----
    __shared__ float sq[4][64];
    __shared__ float ev[64];
    float tot = 0.f;
    #pragma unroll
    for (int bb = 0; bb < 16; ++bb) tot += g_SP2[(v * 16 + bb) * 64 + d];
    sq[v][d] = tot;
    if (tid < 64) ev[tid] = edges_tab[tid] * 0.12f;
    __syncthreads();

    const float* W1 = (v == 0) ? uu_W1 : (v == 1) ? ui_W1 : (v == 2) ? ii_W1 : iu_W1;
    float u = 0.f;
    #pragma unroll
    for (int j = 0; j < 64; ++j) u += sq[v][j] * W1[j * 64 + d];
    g_U[v * 64 + d] = u;

    if (tid < 64) {
        float nv = 0.f;
        #pragma unroll
        for (int j = 0; j < 64; ++j) nv += ev[j] * edge_W[j * 64 + tid];
        nv = nv >= 0.f ? nv : 0.01f * nv;
        g_O3[tid] = 0.5f * (nv + ev[tid]);
    }
    if (tid == 0) g_ctr3 = 0;   // reset for next graph replay (deterministic)
}

// ---------------------------------------------------------------------------
// K4: final elementwise assembly of the three outputs
// ---------------------------------------------------------------------------
__global__ void __launch_bounds__(256) k4_out(float* __restrict__ out)
{
    int idx = blockIdx.x * 256 + threadIdx.x;   // 0..262143
    int r = idx >> 6, d = idx & 63;
    float x_xx   = g_S[(size_t)r * 8 + 0];
    float x_xy_x = g_S[(size_t)r * 8 + 1];
    float y_yy   = g_S[(size_t)r * 8 + 3];
    float y_yx_y = g_S[(size_t)r * 8 + 4];
    float a1 = x_xx * g_U[d];         a1 = a1 >= 0.f ? a1 : 0.01f * a1;
    float a2 = x_xy_x * g_U[64 + d];  a2 = a2 >= 0.f ? a2 : 0.01f * a2;
    float b1 = y_yy * g_U[128 + d];   b1 = b1 >= 0.f ? b1 : 0.01f * b1;
    float b2 = y_yx_y * g_U[192 + d]; b2 = b2 >= 0.f ? b2 : 0.01f * b2;
    out[idx]          = ((a1 + a2) * 0.5f + g_X[idx]) * 0.5f;
    out[262144 + idx] = ((b1 + b2) * 0.5f + g_Y[idx]) * 0.5f;
    out[524288 + idx] = g_O3[d];
}

// ---------------------------------------------------------------------------
// launch (5 kernels)
// ---------------------------------------------------------------------------
extern "C" void kernel_launch(void* const* d_in, const int* in_sizes, int n_in,
                              void* d_out, int out_size)
{
    const int*   user_emb   = (const int*)d_in[0];
    const int*   item_emb   = (const int*)d_in[1];
    const int*   edge_emb   = (const int*)d_in[2];
    const float* gender_tab = (const float*)d_in[3];
    const float* age_tab    = (const float*)d_in[4];
    const float* occ_tab    = (const float*)d_in[5];
    const float* area_tab   = (const float*)d_in[6];
    const float* user_W     = (const float*)d_in[7];
    const float* user_b     = (const float*)d_in[8];
    const float* rate_tab   = (const float*)d_in[9];
    const float* genre_W    = (const float*)d_in[10];
    const float* director_W = (const float*)d_in[11];
    const float* actor_W    = (const float*)d_in[12];
    const float* item_W     = (const float*)d_in[13];
    const float* item_b     = (const float*)d_in[14];
    const float* edges_tab  = (const float*)d_in[15];
    const float* uu_w       = (const float*)d_in[16];
    const float* ui_w       = (const float*)d_in[17];
    const float* iu_w       = (const float*)d_in[18];
    const float* ii_w       = (const float*)d_in[19];
    const float* edge_W     = (const float*)d_in[20];
    const float* uu_W1      = (const float*)d_in[21];
    const float* ui_W1      = (const float*)d_in[22];
    const float* iu_W1      = (const float*)d_in[23];
    const float* ii_W1      = (const float*)d_in[24];
    float* out = (float*)d_out;

    cudaFuncSetAttribute(k1_gemm, cudaFuncAttributeMaxDynamicSharedMemorySize, K1SMEM);

    k0_fold<<<275, 256>>>(genre_W, director_W, actor_W, item_W,
                          gender_tab, age_tab, occ_tab, area_tab, user_W, rate_tab);
    k1_gemm<<<dim3(32, 9), 256, K1SMEM>>>(item_emb);
    k2_finalize<<<1024, 256>>>(user_emb, item_emb, edge_emb, user_b, item_b, edges_tab,
                               uu_w, ui_w, iu_w, ii_w);
    k3_reduce<<<16, 256>>>(uu_W1, ui_W1, ii_W1, iu_W1, edge_W, edges_tab);
    k4_out<<<1024, 256>>>(out);
}